// round 9
// baseline (speedup 1.0000x reference)
#include <cuda_runtime.h>
#include <cstdint>

#define HDIM   2048
#define NEXP   64
#define KSEL   8
#define SEQ    4096
#define NB     4
#define NTOK   16384          // NB*SEQ
#define TILE_M 64
#define KC     32
#define XSTR   36             // smem row stride (floats): 144B -> conflict-free 16B steps
#define NBLK   (NTOK / TILE_M)   // 256 blocks
#define OUT_W    ((size_t)NTOK * KSEL)        // 131072
#define OUT_LOSS ((size_t)2 * NTOK * KSEL)    // 262144
#define OUT_LOAD (OUT_LOSS + 1)               // 262145
#define TAU    2e-5f          // near-tie flag threshold (~20x fp32 GEMM noise)

// Deterministic per-block partials (written, not accumulated -> no init kernel needed)
__device__ float g_Pp[NBLK * NEXP];
__device__ int   g_Cp[NBLK * NEXP];
__device__ unsigned char g_flag[NTOK];   // 1 = near-tie token -> ensemble revote

__device__ __forceinline__ float sigm(float x) {
    return 1.0f / (1.0f + expf(-x));
}

// ============================ pass 1: GEMM + select ============================
__global__ __launch_bounds__(256, 2)
void gate_main(const float* __restrict__ x,
               const float* __restrict__ w,
               const float* __restrict__ bias,
               float* __restrict__ out) {
    __shared__ __align__(16) unsigned char smraw[TILE_M * XSTR * 2 * 4];
    float* xs = (float*)smraw;
    float* ws = xs + TILE_M * XSTR;

    const int tid   = threadIdx.x;
    const int m0    = blockIdx.x * TILE_M;
    const int warp  = tid >> 5, lane = tid & 31;
    const int warpM = warp & 1;        // token half   (0..1)  -> 32 tokens
    const int warpN = warp >> 1;       // expert quad  (0..3)  -> 16 experts
    const int tg    = lane >> 2;       // 0..7 token group
    const int eg    = lane & 3;        // 0..3 expert group

    const int lrow = tid >> 2;
    const int lcol = (tid & 3) * 8;
    const float* gx = x + (size_t)(m0 + lrow) * HDIM + lcol;
    const float* gw = w + (size_t)lrow * HDIM + lcol;
    float* sxp = xs + lrow * XSTR + lcol;
    float* swp = ws + lrow * XSTR + lcol;

    // grain-4/stride-16 4-chain ordering (best single ordering so far)
    float acc[4][4][4];
#pragma unroll
    for (int i = 0; i < 4; i++)
#pragma unroll
        for (int j = 0; j < 4; j++)
#pragma unroll
            for (int s = 0; s < 4; s++) acc[i][j][s] = 0.0f;

    float4 px0 = *(const float4*)(gx);
    float4 px1 = *(const float4*)(gx + 4);
    float4 pw0 = *(const float4*)(gw);
    float4 pw1 = *(const float4*)(gw + 4);

    const float* xsp = xs + (warpM * 32 + tg) * XSTR;
    const float* wsp = ws + (warpN * 16 + eg) * XSTR;

    for (int kc = 0; kc < HDIM / KC; ++kc) {
        *(float4*)sxp       = px0;
        *(float4*)(sxp + 4) = px1;
        *(float4*)swp       = pw0;
        *(float4*)(swp + 4) = pw1;
        __syncthreads();
        if (kc + 1 < HDIM / KC) {
            const int k0 = (kc + 1) * KC;
            px0 = *(const float4*)(gx + k0);
            px1 = *(const float4*)(gx + k0 + 4);
            pw0 = *(const float4*)(gw + k0);
            pw1 = *(const float4*)(gw + k0 + 4);
        }
#pragma unroll
        for (int c = 0; c < KC; c += 4) {
            const int s = (c >> 2) & 3;
            float4 xv[4], wv[4];
#pragma unroll
            for (int it = 0; it < 4; it++)
                xv[it] = *(const float4*)(xsp + it * 8 * XSTR + c);
#pragma unroll
            for (int ie = 0; ie < 4; ie++)
                wv[ie] = *(const float4*)(wsp + ie * 4 * XSTR + c);
#pragma unroll
            for (int cc = 0; cc < 4; cc++) {
#pragma unroll
                for (int it = 0; it < 4; it++) {
                    const float xa = (cc == 0) ? xv[it].x : (cc == 1) ? xv[it].y
                                   : (cc == 2) ? xv[it].z : xv[it].w;
#pragma unroll
                    for (int ie = 0; ie < 4; ie++) {
                        const float wa = (cc == 0) ? wv[ie].x : (cc == 1) ? wv[ie].y
                                       : (cc == 2) ? wv[ie].z : wv[ie].w;
                        acc[it][ie][s] = fmaf(xa, wa, acc[it][ie][s]);
                    }
                }
            }
        }
        __syncthreads();
    }

    // ---- epilogue ----
    float* lt    = (float*)smraw;          // [64][65]
    float* sbias = lt + 64 * 65;           // [64]
    int*   sC    = (int*)(sbias + 64);     // [64]

#pragma unroll
    for (int it = 0; it < 4; it++) {
        const int t = warpM * 32 + tg + it * 8;
#pragma unroll
        for (int ie = 0; ie < 4; ie++) {
            const int e = warpN * 16 + eg + ie * 4;
            const float p02 = acc[it][ie][0] + acc[it][ie][2];
            const float p13 = acc[it][ie][1] + acc[it][ie][3];
            lt[t * 65 + e] = p02 + p13;
        }
    }
    if (tid < NEXP) { sbias[tid] = bias[tid]; sC[tid] = 0; }
    __syncthreads();

    if (tid < TILE_M) {
        const int j = tid;
        float* row = lt + j * 65;

        float ssum = 0.0f;
#pragma unroll 8
        for (int e = 0; e < NEXP; e++) ssum += sigm(row[e]);

        // top-9: first 8 = selection; 9th gives the boundary gap
        unsigned long long used = 0ull;
        int   isel[KSEL];
        float bestv[KSEL + 1];
        float wsel[KSEL];
        float wsum = 0.0f;
        for (int k = 0; k < KSEL + 1; k++) {
            float best = -3.402823466e38f;
            int   bi   = 0;
            for (int e = 0; e < NEXP; e++) {
                if (!((used >> e) & 1ull)) {
                    const float bl = row[e] + sbias[e];
                    if (bl > best) { best = bl; bi = e; }
                }
            }
            used |= 1ull << bi;
            bestv[k] = best;
            if (k < KSEL) {
                isel[k] = bi;
                const float sc = sigm(row[bi]);
                wsel[k] = sc;
                wsum += sc;
            }
        }
        float minGap = 3.402823466e38f;
#pragma unroll
        for (int k = 0; k < KSEL; k++) {
            const float g = bestv[k] - bestv[k + 1];
            minGap = (g < minGap) ? g : minGap;
        }
        g_flag[m0 + j] = (minGap < TAU) ? 1 : 0;

        const float inv = 1.0f / (wsum + 1e-10f);
        float* oi = out + (size_t)(m0 + j) * KSEL;
        float* ow = out + OUT_W + (size_t)(m0 + j) * KSEL;
#pragma unroll
        for (int k = 0; k < KSEL; k++) {
            oi[k] = (float)isel[k];
            ow[k] = wsel[k] * inv;
            atomicAdd(&sC[isel[k]], 1);
        }
        const float pin = 1.0f / (ssum + 1e-10f);
        for (int e = 0; e < NEXP; e++) row[e] = sigm(row[e]) * pin;
    }
    __syncthreads();

    if (tid < NEXP) {
        float ps = 0.0f;
        for (int j = 0; j < TILE_M; j++) ps += lt[j * 65 + tid];
        g_Pp[blockIdx.x * NEXP + tid] = ps;
        g_Cp[blockIdx.x * NEXP + tid] = sC[tid];
    }
}

// ================== pass 2: ensemble re-vote for flagged tokens ==================
// Recompute the 64 logits under 5 fp32 accumulation orderings, take the
// element-wise median (~pairwise majority for near-ties), redo top-8.
__global__ __launch_bounds__(256, 2)
void gate_vote(const float* __restrict__ x,
               const float* __restrict__ w,
               const float* __restrict__ bias,
               float* __restrict__ out) {
    __shared__ float sx[HDIM];        // 8 KB
    __shared__ float sw[NEXP * 32];   // 8 KB
    __shared__ float sL[NEXP];
    __shared__ float sb[NEXP];
    const int tid = threadIdx.x;
    const int t0  = blockIdx.x * TILE_M;
    if (tid < NEXP) sb[tid] = bias[tid];

    for (int j = 0; j < TILE_M; j++) {
        const int tok = t0 + j;
        if (!g_flag[tok]) continue;      // uniform across block

        for (int i = tid; i < HDIM; i += 256)
            sx[i] = x[(size_t)tok * HDIM + i];

        // chains (all k-ascending):
        float aS = 0.0f;                 // V1 sequential (never reset)
        float aH = 0.0f;                 // running, reset at k=1024 -> V3 split-2
        float aQ = 0.0f;                 // running, reset every 512 -> V4 split-4
        float g16a = 0.0f, g16b = 0.0f, g16c = 0.0f, g16d = 0.0f;   // V2 grain4/16
        float g32_0 = 0, g32_1 = 0, g32_2 = 0, g32_3 = 0,           // V5 grain4/32
              g32_4 = 0, g32_5 = 0, g32_6 = 0, g32_7 = 0;
        float p2_0 = 0, p4_0 = 0, p4_1 = 0, p4_2 = 0;

        for (int c = 0; c < HDIM / 32; c++) {
            __syncthreads();             // sw (and at c=0: sx/sL) safe to (re)use
            for (int i = tid; i < NEXP * 32; i += 256) {
                const int e  = i >> 5;
                const int kk = i & 31;
                sw[i] = w[(size_t)e * HDIM + c * 32 + kk];
            }
            __syncthreads();
            if (tid < NEXP) {
#pragma unroll
                for (int kk = 0; kk < 32; kk++) {
                    const float xa = sx[c * 32 + kk];
                    const float wa = sw[tid * 32 + kk];
                    aS = fmaf(xa, wa, aS);
                    aH = fmaf(xa, wa, aH);
                    aQ = fmaf(xa, wa, aQ);
                    const int q = kk >> 2;           // compile-time in unrolled loop
                    if ((q & 3) == 0) g16a = fmaf(xa, wa, g16a);
                    else if ((q & 3) == 1) g16b = fmaf(xa, wa, g16b);
                    else if ((q & 3) == 2) g16c = fmaf(xa, wa, g16c);
                    else                   g16d = fmaf(xa, wa, g16d);
                    if      (q == 0) g32_0 = fmaf(xa, wa, g32_0);
                    else if (q == 1) g32_1 = fmaf(xa, wa, g32_1);
                    else if (q == 2) g32_2 = fmaf(xa, wa, g32_2);
                    else if (q == 3) g32_3 = fmaf(xa, wa, g32_3);
                    else if (q == 4) g32_4 = fmaf(xa, wa, g32_4);
                    else if (q == 5) g32_5 = fmaf(xa, wa, g32_5);
                    else if (q == 6) g32_6 = fmaf(xa, wa, g32_6);
                    else             g32_7 = fmaf(xa, wa, g32_7);
                }
                if (c == 15) { p4_0 = aQ; aQ = 0.0f; }
                if (c == 31) { p4_1 = aQ; aQ = 0.0f; p2_0 = aH; aH = 0.0f; }
                if (c == 47) { p4_2 = aQ; aQ = 0.0f; }
            }
        }
        __syncthreads();
        if (tid < NEXP) {
            const float L1 = aS;
            const float L2 = (g16a + g16c) + (g16b + g16d);
            const float L3 = p2_0 + aH;
            const float L4 = ((p4_0 + p4_1) + p4_2) + aQ;
            const float L5 = ((g32_0 + g32_1) + (g32_2 + g32_3))
                           + ((g32_4 + g32_5) + (g32_6 + g32_7));
            // median of 5
            float v[5] = {L1, L2, L3, L4, L5};
#pragma unroll
            for (int a = 0; a < 4; a++)
#pragma unroll
                for (int b = 0; b < 4 - a; b++)
                    if (v[b] > v[b + 1]) { const float t = v[b]; v[b] = v[b + 1]; v[b + 1] = t; }
            sL[tid] = v[2];
        }
        __syncthreads();

        if (tid == 0) {
            unsigned long long used = 0ull;
            int   isel[KSEL];
            float wsel[KSEL];
            float wsum = 0.0f;
            for (int k = 0; k < KSEL; k++) {
                float best = -3.402823466e38f;
                int   bi   = 0;
                for (int e = 0; e < NEXP; e++) {
                    if (!((used >> e) & 1ull)) {
                        const float bl = sL[e] + sb[e];
                        if (bl > best) { best = bl; bi = e; }
                    }
                }
                used |= 1ull << bi;
                isel[k] = bi;
                const float sc = sigm(sL[bi]);
                wsel[k] = sc;
                wsum += sc;
            }
            const float inv = 1.0f / (wsum + 1e-10f);
            for (int k = 0; k < KSEL; k++) {
                out[(size_t)tok * KSEL + k]         = (float)isel[k];
                out[OUT_W + (size_t)tok * KSEL + k] = wsel[k] * inv;
            }
        }
        __syncthreads();
    }
}

// ============================ pass 3: reductions ============================
__global__ void gate_final(float* __restrict__ out) {
    __shared__ float red[NEXP];
    const int e = threadIdx.x;
    if (e < NEXP) {
        long long load = 0;
        float part = 0.0f;
        for (int b = 0; b < NB; b++) {
            int   cb = 0;
            float pb = 0.0f;
            const int base = b * (SEQ / TILE_M);
            for (int blk = 0; blk < SEQ / TILE_M; blk++) {
                const int g = (base + blk) * NEXP + e;
                cb += g_Cp[g];
                pb += g_Pp[g];
            }
            load += cb;
            const float fi = (float)cb / (float)(KSEL * SEQ);
            const float Pi = pb / (float)SEQ;
            part += fi * Pi;
        }
        out[OUT_LOAD + e] = (float)load;
        red[e] = part;
    }
    __syncthreads();
    if (e == 0) {
        float s = 0.0f;
        for (int i = 0; i < NEXP; i++) s += red[i];
        out[OUT_LOSS] = 0.01f * s / (float)NB;   // SEQ_ALPHA * mean over batch
    }
}

extern "C" void kernel_launch(void* const* d_in, const int* in_sizes, int n_in,
                              void* d_out, int out_size) {
    const float* x    = (const float*)d_in[0];
    const float* w    = (const float*)d_in[1];
    const float* bias = (const float*)d_in[2];
    float* out = (float*)d_out;
    (void)in_sizes; (void)n_in; (void)out_size;

    gate_main<<<NBLK, 256>>>(x, w, bias, out);
    gate_vote<<<NBLK, 256>>>(x, w, bias, out);
    gate_final<<<1, NEXP>>>(out);
}

// round 11
// speedup vs baseline: 1.0176x; 1.0176x over previous
#include <cuda_runtime.h>
#include <cstdint>

#define HDIM   2048
#define NEXP   64
#define KSEL   8
#define SEQ    4096
#define NB     4
#define NTOK   16384          // NB*SEQ
#define TILE_M 64
#define KC     32
#define NBLK   (NTOK / TILE_M)   // 256 blocks
#define OUT_W    ((size_t)NTOK * KSEL)        // 131072
#define OUT_LOSS ((size_t)2 * NTOK * KSEL)    // 262144
#define OUT_LOAD (OUT_LOSS + 1)               // 262145
#define TAU    2e-5f          // near-tie flag threshold
#define VGRID  128
#define XDS    68             // xd row stride (floats): 272B = 16B multiple, phase shift 16B
#define WTS    66             // wt row stride (floats): 264B, 8B loads only

__device__ float g_Pp[NBLK * NEXP];
__device__ int   g_Cp[NBLK * NEXP];
__device__ unsigned char g_flag[NTOK];
__device__ int   g_nflag;
__device__ int   g_list[NTOK];

__device__ __forceinline__ float sigm(float x) {
    return 1.0f / (1.0f + expf(-x));
}

__device__ __forceinline__ void ffma2(unsigned long long& d,
                                      unsigned long long a,
                                      unsigned long long b) {
    asm volatile("fma.rn.f32x2 %0, %1, %2, %0;" : "+l"(d) : "l"(a), "l"(b));
}

// ============================ pass 1: GEMM + select ============================
// Packed-expert FFMA2 GEMM. Per-lane math is bit-identical to the R9 pass-1
// ordering: per (token,expert) 4 chains, slice s=(k>>2)&3, k ascending per
// chain, reduce (s0+s2)+(s1+s3).
__global__ __launch_bounds__(256, 2)
void gate_main(const float* __restrict__ x,
               const float* __restrict__ w,
               const float* __restrict__ bias,
               float* __restrict__ out) {
    // xd: 64 tokens x 32k duplicated {x,x} (row XDS=68 floats) = 4352 floats
    // wt: 32 k x 64 experts transposed (row WTS=66 floats)     = 2112 floats
    // epilogue aliases: lt[64][65] + sbias[64] + sC[64] = 4288 floats
    __shared__ __align__(16) float smraw[64 * XDS + 32 * WTS];
    float* xd = smraw;
    float* wt = smraw + 64 * XDS;

    const int tid   = threadIdx.x;
    const int m0    = blockIdx.x * TILE_M;
    const int warp  = tid >> 5, lane = tid & 31;
    const int warpM = warp & 1;        // token half (0..1) -> 32 tokens
    const int warpN = warp >> 1;       // expert quad (0..3) -> 16 experts
    const int tg    = lane >> 2;       // 0..7 token group
    const int eg    = lane & 3;        // 0..3 expert pair group

    // experts: pair A = (eA, eA+1), pair B = (eA+8, eA+9)
    const int eA = warpN * 16 + eg * 2;

    // staging: 256 threads cover 64 rows x 32 cols (8 floats each)
    const int lrow = tid >> 2;
    const int lcol = (tid & 3) * 8;
    const float* gx = x + (size_t)(m0 + lrow) * HDIM + lcol;
    const float* gw = w + (size_t)lrow * HDIM + lcol;

    unsigned long long acc2[4][2][4];   // [token it][expert pair][slice]
#pragma unroll
    for (int i = 0; i < 4; i++)
#pragma unroll
        for (int p = 0; p < 2; p++)
#pragma unroll
            for (int s = 0; s < 4; s++) acc2[i][p][s] = 0ull;

    float4 px0 = *(const float4*)(gx);
    float4 px1 = *(const float4*)(gx + 4);
    float4 pw0 = *(const float4*)(gw);
    float4 pw1 = *(const float4*)(gw + 4);

    int xoff[4];
#pragma unroll
    for (int it = 0; it < 4; it++)
        xoff[it] = (warpM * 32 + tg + it * 8) * XDS;
    const float* wtA = wt + eA;
    const float* wtB = wt + eA + 8;

    float* xdw = xd + lrow * XDS + lcol * 2;
    float* wtw = wt + lrow;   // column e=lrow; +WTS per k

    for (int kc = 0; kc < HDIM / KC; ++kc) {
        // x duplicated {a,a,b,b}
        *(float4*)(xdw + 0)  = make_float4(px0.x, px0.x, px0.y, px0.y);
        *(float4*)(xdw + 4)  = make_float4(px0.z, px0.z, px0.w, px0.w);
        *(float4*)(xdw + 8)  = make_float4(px1.x, px1.x, px1.y, px1.y);
        *(float4*)(xdw + 12) = make_float4(px1.z, px1.z, px1.w, px1.w);
        // w transposed: wt[k][e]
        wtw[(lcol + 0) * WTS] = pw0.x;
        wtw[(lcol + 1) * WTS] = pw0.y;
        wtw[(lcol + 2) * WTS] = pw0.z;
        wtw[(lcol + 3) * WTS] = pw0.w;
        wtw[(lcol + 4) * WTS] = pw1.x;
        wtw[(lcol + 5) * WTS] = pw1.y;
        wtw[(lcol + 6) * WTS] = pw1.z;
        wtw[(lcol + 7) * WTS] = pw1.w;
        __syncthreads();
        if (kc + 1 < HDIM / KC) {
            const int k0 = (kc + 1) * KC;
            px0 = *(const float4*)(gx + k0);
            px1 = *(const float4*)(gx + k0 + 4);
            pw0 = *(const float4*)(gw + k0);
            pw1 = *(const float4*)(gw + k0 + 4);
        }
#pragma unroll
        for (int c = 0; c < KC; c += 4) {
            const int s = (c >> 2) & 3;
            unsigned long long wA[4], wB[4];
#pragma unroll
            for (int cc = 0; cc < 4; cc++) {
                wA[cc] = *(const unsigned long long*)(wtA + (c + cc) * WTS);
                wB[cc] = *(const unsigned long long*)(wtB + (c + cc) * WTS);
            }
#pragma unroll
            for (int it = 0; it < 4; it++) {
                // two LDS.128 (16B-aligned: t*272 + 8c): {xc,xc,xc1,xc1},{xc2,xc2,xc3,xc3}
                const ulonglong2 xp0 = *(const ulonglong2*)(xd + xoff[it] + 2 * c);
                const ulonglong2 xp1 = *(const ulonglong2*)(xd + xoff[it] + 2 * c + 4);
                ffma2(acc2[it][0][s], xp0.x, wA[0]);
                ffma2(acc2[it][1][s], xp0.x, wB[0]);
                ffma2(acc2[it][0][s], xp0.y, wA[1]);
                ffma2(acc2[it][1][s], xp0.y, wB[1]);
                ffma2(acc2[it][0][s], xp1.x, wA[2]);
                ffma2(acc2[it][1][s], xp1.x, wB[2]);
                ffma2(acc2[it][0][s], xp1.y, wA[3]);
                ffma2(acc2[it][1][s], xp1.y, wB[3]);
            }
        }
        __syncthreads();
    }

    // ---- epilogue (aliases smem; last mainloop sync covers it) ----
    float* lt    = smraw;              // [64][65]
    float* sbias = lt + 64 * 65;       // [64]
    int*   sC    = (int*)(sbias + 64); // [64]

#pragma unroll
    for (int it = 0; it < 4; it++) {
        const int t = warpM * 32 + tg + it * 8;
#pragma unroll
        for (int p = 0; p < 2; p++) {
            float lo[4], hi[4];
#pragma unroll
            for (int s = 0; s < 4; s++) {
                const unsigned long long a = acc2[it][p][s];
                lo[s] = __uint_as_float((unsigned)(a & 0xffffffffull));
                hi[s] = __uint_as_float((unsigned)(a >> 32));
            }
            const int e0 = eA + p * 8;
            lt[t * 65 + e0]     = (lo[0] + lo[2]) + (lo[1] + lo[3]);
            lt[t * 65 + e0 + 1] = (hi[0] + hi[2]) + (hi[1] + hi[3]);
        }
    }
    if (tid < NEXP) { sbias[tid] = bias[tid]; sC[tid] = 0; }
    __syncthreads();

    if (tid < TILE_M) {
        const int j = tid;
        float* row = lt + j * 65;

        float ssum = 0.0f;
#pragma unroll 8
        for (int e = 0; e < NEXP; e++) ssum += sigm(row[e]);

        unsigned long long used = 0ull;
        int   isel[KSEL];
        float bestv[KSEL + 1];
        float wsel[KSEL];
        float wsum = 0.0f;
        for (int k = 0; k < KSEL + 1; k++) {
            float best = -3.402823466e38f;
            int   bi   = 0;
            for (int e = 0; e < NEXP; e++) {
                if (!((used >> e) & 1ull)) {
                    const float bl = row[e] + sbias[e];
                    if (bl > best) { best = bl; bi = e; }
                }
            }
            used |= 1ull << bi;
            bestv[k] = best;
            if (k < KSEL) {
                isel[k] = bi;
                const float sc = sigm(row[bi]);
                wsel[k] = sc;
                wsum += sc;
            }
        }
        float minGap = 3.402823466e38f;
#pragma unroll
        for (int k = 0; k < KSEL; k++) {
            const float g = bestv[k] - bestv[k + 1];
            minGap = (g < minGap) ? g : minGap;
        }
        g_flag[m0 + j] = (minGap < TAU) ? 1 : 0;

        const float inv = 1.0f / (wsum + 1e-10f);
        float* oi = out + (size_t)(m0 + j) * KSEL;
        float* ow = out + OUT_W + (size_t)(m0 + j) * KSEL;
#pragma unroll
        for (int k = 0; k < KSEL; k++) {
            oi[k] = (float)isel[k];
            ow[k] = wsel[k] * inv;
            atomicAdd(&sC[isel[k]], 1);
        }
        const float pin = 1.0f / (ssum + 1e-10f);
        for (int e = 0; e < NEXP; e++) row[e] = sigm(row[e]) * pin;
    }
    __syncthreads();

    if (tid < NEXP) {
        float ps = 0.0f;
        for (int j = 0; j < TILE_M; j++) ps += lt[j * 65 + tid];
        g_Pp[blockIdx.x * NEXP + tid] = ps;
        g_Cp[blockIdx.x * NEXP + tid] = sC[tid];
    }
}

// ================== compaction: deterministic flagged-token list ==================
__global__ void gate_compact() {
    __shared__ int cnt[256];
    __shared__ int off[256];
    const int tid = threadIdx.x;
    const int per = NTOK / 256;    // 64
    int c = 0;
    for (int i = 0; i < per; i++) c += g_flag[tid * per + i];
    cnt[tid] = c;
    __syncthreads();
    if (tid == 0) {
        int r = 0;
        for (int i = 0; i < 256; i++) { off[i] = r; r += cnt[i]; }
        g_nflag = r;
    }
    __syncthreads();
    int o = off[tid];
    for (int i = 0; i < per; i++) {
        const int t = tid * per + i;
        if (g_flag[t]) g_list[o++] = t;
    }
}

// ================== pass 2: ensemble re-vote, one token per block ==================
// 5 fp32 orderings per expert (chains bit-identical to R9's gate_vote),
// element-wise median, redo top-8. Warps 0-1 compute (1 expert/thread, all
// chains); warps 4-7 double-buffer the w chunks.
__global__ __launch_bounds__(256, 1)
void gate_vote(const float* __restrict__ x,
               const float* __restrict__ w,
               const float* __restrict__ bias,
               float* __restrict__ out) {
    __shared__ float sx[HDIM];           // 8 KB
    __shared__ float swb[2][64 * 33];    // 16.9 KB, stride 33 -> conflict-free lane=e reads
    __shared__ float sL[NEXP];
    __shared__ float sb[NEXP];
    const int tid = threadIdx.x;
    if (tid < NEXP) sb[tid] = bias[tid];
    const int nf = g_nflag;

    for (int idx = blockIdx.x; idx < nf; idx += VGRID) {
        const int tok = g_list[idx];
        __syncthreads();   // protect smem reuse across list iterations
        for (int i = tid; i < HDIM; i += 256)
            sx[i] = x[(size_t)tok * HDIM + i];
        if (tid >= 128) {           // prologue: fill buffer 0 (chunk 0)
            const int p = tid - 128;
#pragma unroll
            for (int r = 0; r < 4; r++) {
                const int f4 = p + r * 128;
                const int e = f4 >> 3, q = f4 & 7;
                const float4 v = *(const float4*)(w + (size_t)e * HDIM + q * 4);
                swb[0][e * 33 + q * 4 + 0] = v.x;
                swb[0][e * 33 + q * 4 + 1] = v.y;
                swb[0][e * 33 + q * 4 + 2] = v.z;
                swb[0][e * 33 + q * 4 + 3] = v.w;
            }
        }
        __syncthreads();

        float aS = 0.0f, aH = 0.0f, aQ = 0.0f;
        float g16a = 0, g16b = 0, g16c = 0, g16d = 0;
        float g32_0 = 0, g32_1 = 0, g32_2 = 0, g32_3 = 0,
              g32_4 = 0, g32_5 = 0, g32_6 = 0, g32_7 = 0;
        float p2_0 = 0, p4_0 = 0, p4_1 = 0, p4_2 = 0;

        for (int c = 0; c < HDIM / 32; c++) {
            const int cur = c & 1;
            if (tid < 64) {
                const float* wrow = &swb[cur][tid * 33];
                const float* xrow = &sx[c * 32];
#pragma unroll
                for (int kk = 0; kk < 32; kk++) {
                    const float xa = xrow[kk];
                    const float wa = wrow[kk];
                    aS = fmaf(xa, wa, aS);
                    aH = fmaf(xa, wa, aH);
                    aQ = fmaf(xa, wa, aQ);
                    const int q = kk >> 2;
                    if ((q & 3) == 0)      g16a = fmaf(xa, wa, g16a);
                    else if ((q & 3) == 1) g16b = fmaf(xa, wa, g16b);
                    else if ((q & 3) == 2) g16c = fmaf(xa, wa, g16c);
                    else                   g16d = fmaf(xa, wa, g16d);
                    if      (q == 0) g32_0 = fmaf(xa, wa, g32_0);
                    else if (q == 1) g32_1 = fmaf(xa, wa, g32_1);
                    else if (q == 2) g32_2 = fmaf(xa, wa, g32_2);
                    else if (q == 3) g32_3 = fmaf(xa, wa, g32_3);
                    else if (q == 4) g32_4 = fmaf(xa, wa, g32_4);
                    else if (q == 5) g32_5 = fmaf(xa, wa, g32_5);
                    else if (q == 6) g32_6 = fmaf(xa, wa, g32_6);
                    else             g32_7 = fmaf(xa, wa, g32_7);
                }
                if (c == 15) { p4_0 = aQ; aQ = 0.0f; }
                if (c == 31) { p4_1 = aQ; aQ = 0.0f; p2_0 = aH; aH = 0.0f; }
                if (c == 47) { p4_2 = aQ; aQ = 0.0f; }
            } else if (tid >= 128 && c + 1 < HDIM / 32) {
                const int p = tid - 128;
#pragma unroll
                for (int r = 0; r < 4; r++) {
                    const int f4 = p + r * 128;
                    const int e = f4 >> 3, q = f4 & 7;
                    const float4 v = *(const float4*)(w + (size_t)e * HDIM + (c + 1) * 32 + q * 4);
                    swb[cur ^ 1][e * 33 + q * 4 + 0] = v.x;
                    swb[cur ^ 1][e * 33 + q * 4 + 1] = v.y;
                    swb[cur ^ 1][e * 33 + q * 4 + 2] = v.z;
                    swb[cur ^ 1][e * 33 + q * 4 + 3] = v.w;
                }
            }
            __syncthreads();
        }

        if (tid < NEXP) {
            const float L1 = aS;
            const float L2 = (g16a + g16c) + (g16b + g16d);
            const float L3 = p2_0 + aH;
            const float L4 = ((p4_0 + p4_1) + p4_2) + aQ;
            const float L5 = ((g32_0 + g32_1) + (g32_2 + g32_3))
                           + ((g32_4 + g32_5) + (g32_6 + g32_7));
            float v[5] = {L1, L2, L3, L4, L5};
#pragma unroll
            for (int a = 0; a < 4; a++)
#pragma unroll
                for (int b = 0; b < 4 - a; b++)
                    if (v[b] > v[b + 1]) { const float t = v[b]; v[b] = v[b + 1]; v[b + 1] = t; }
            sL[tid] = v[2];
        }
        __syncthreads();

        if (tid == 0) {
            unsigned long long used = 0ull;
            int   isel[KSEL];
            float wsel[KSEL];
            float wsum = 0.0f;
            for (int k = 0; k < KSEL; k++) {
                float best = -3.402823466e38f;
                int   bi   = 0;
                for (int e = 0; e < NEXP; e++) {
                    if (!((used >> e) & 1ull)) {
                        const float bl = sL[e] + sb[e];
                        if (bl > best) { best = bl; bi = e; }
                    }
                }
                used |= 1ull << bi;
                isel[k] = bi;
                const float sc = sigm(sL[bi]);
                wsel[k] = sc;
                wsum += sc;
            }
            const float inv = 1.0f / (wsum + 1e-10f);
            for (int k = 0; k < KSEL; k++) {
                out[(size_t)tok * KSEL + k]         = (float)isel[k];
                out[OUT_W + (size_t)tok * KSEL + k] = wsel[k] * inv;
            }
        }
    }
}

// ============================ pass 3: reductions ============================
__global__ void gate_final(float* __restrict__ out) {
    __shared__ float sP[NB][NEXP];
    __shared__ int   sCt[NB][NEXP];
    __shared__ float red[NEXP];
    const int tid = threadIdx.x;
    const int e = tid & 63;
    const int b = tid >> 6;      // batch 0..3
    int   cb = 0;
    float pb = 0.0f;
    const int base = b * (SEQ / TILE_M);
    for (int blk = 0; blk < SEQ / TILE_M; blk++) {
        const int g = (base + blk) * NEXP + e;
        cb += g_Cp[g];
        pb += g_Pp[g];
    }
    sCt[b][e] = cb;
    sP[b][e]  = pb;
    __syncthreads();
    if (tid < NEXP) {
        long long load = 0;
        float part = 0.0f;
        for (int bb = 0; bb < NB; bb++) {
            const int c = sCt[bb][tid];
            load += c;
            const float fi = (float)c / (float)(KSEL * SEQ);
            const float Pi = sP[bb][tid] / (float)SEQ;
            part += fi * Pi;
        }
        out[OUT_LOAD + tid] = (float)load;
        red[tid] = part;
    }
    __syncthreads();
    if (tid == 0) {
        float s = 0.0f;
        for (int i = 0; i < NEXP; i++) s += red[i];
        out[OUT_LOSS] = 0.01f * s / (float)NB;   // SEQ_ALPHA * mean over batch
    }
}

extern "C" void kernel_launch(void* const* d_in, const int* in_sizes, int n_in,
                              void* d_out, int out_size) {
    const float* x    = (const float*)d_in[0];
    const float* w    = (const float*)d_in[1];
    const float* bias = (const float*)d_in[2];
    float* out = (float*)d_out;
    (void)in_sizes; (void)n_in; (void)out_size;

    gate_main<<<NBLK, 256>>>(x, w, bias, out);
    gate_compact<<<1, 256>>>();
    gate_vote<<<VGRID, 256>>>(x, w, bias, out);
    gate_final<<<1, 256>>>(out);
}

// round 12
// speedup vs baseline: 1.2430x; 1.2215x over previous
#include <cuda_runtime.h>
#include <cstdint>

#define HDIM   2048
#define NEXP   64
#define KSEL   8
#define SEQ    4096
#define NB     4
#define NTOK   16384          // NB*SEQ
#define TILE_M 64
#define KC     32
#define XSTR   36             // smem row stride (floats): 144B -> conflict-free 16B steps
#define NBLK   (NTOK / TILE_M)   // 256 blocks
#define OUT_W    ((size_t)NTOK * KSEL)        // 131072
#define OUT_LOSS ((size_t)2 * NTOK * KSEL)    // 262144
#define OUT_LOAD (OUT_LOSS + 1)               // 262145
#define TAU    2e-5f          // near-tie flag threshold
#define VGRID  128

__device__ float g_Pp[NBLK * NEXP];
__device__ int   g_Cp[NBLK * NEXP];
__device__ unsigned char g_flag[NTOK];
__device__ int   g_nflag;
__device__ int   g_list[NTOK];

__device__ __forceinline__ float sigm(float x) {
    return 1.0f / (1.0f + expf(-x));
}

// ============================ pass 1: GEMM + select ============================
// Scalar 4-chain GEMM (R9-verified): per (token,expert) 4 fp32 chains,
// slice s=(k>>2)&3, k ascending per chain, reduce (s0+s2)+(s1+s3).
__global__ __launch_bounds__(256, 2)
void gate_main(const float* __restrict__ x,
               const float* __restrict__ w,
               const float* __restrict__ bias,
               float* __restrict__ out) {
    __shared__ __align__(16) unsigned char smraw[TILE_M * XSTR * 2 * 4];
    float* xs = (float*)smraw;
    float* ws = xs + TILE_M * XSTR;

    const int tid   = threadIdx.x;
    const int m0    = blockIdx.x * TILE_M;
    const int warp  = tid >> 5, lane = tid & 31;
    const int warpM = warp & 1;        // token half (0..1) -> 32 tokens
    const int warpN = warp >> 1;       // expert quad (0..3) -> 16 experts
    const int tg    = lane >> 2;       // 0..7 token group
    const int eg    = lane & 3;        // 0..3 expert group

    const int lrow = tid >> 2;
    const int lcol = (tid & 3) * 8;
    const float* gx = x + (size_t)(m0 + lrow) * HDIM + lcol;
    const float* gw = w + (size_t)lrow * HDIM + lcol;
    float* sxp = xs + lrow * XSTR + lcol;
    float* swp = ws + lrow * XSTR + lcol;

    float acc[4][4][4];
#pragma unroll
    for (int i = 0; i < 4; i++)
#pragma unroll
        for (int j = 0; j < 4; j++)
#pragma unroll
            for (int s = 0; s < 4; s++) acc[i][j][s] = 0.0f;

    float4 px0 = *(const float4*)(gx);
    float4 px1 = *(const float4*)(gx + 4);
    float4 pw0 = *(const float4*)(gw);
    float4 pw1 = *(const float4*)(gw + 4);

    const float* xsp = xs + (warpM * 32 + tg) * XSTR;
    const float* wsp = ws + (warpN * 16 + eg) * XSTR;

    for (int kc = 0; kc < HDIM / KC; ++kc) {
        *(float4*)sxp       = px0;
        *(float4*)(sxp + 4) = px1;
        *(float4*)swp       = pw0;
        *(float4*)(swp + 4) = pw1;
        __syncthreads();
        if (kc + 1 < HDIM / KC) {
            const int k0 = (kc + 1) * KC;
            px0 = *(const float4*)(gx + k0);
            px1 = *(const float4*)(gx + k0 + 4);
            pw0 = *(const float4*)(gw + k0);
            pw1 = *(const float4*)(gw + k0 + 4);
        }
#pragma unroll
        for (int c = 0; c < KC; c += 4) {
            const int s = (c >> 2) & 3;
            float4 xv[4], wv[4];
#pragma unroll
            for (int it = 0; it < 4; it++)
                xv[it] = *(const float4*)(xsp + it * 8 * XSTR + c);
#pragma unroll
            for (int ie = 0; ie < 4; ie++)
                wv[ie] = *(const float4*)(wsp + ie * 4 * XSTR + c);
#pragma unroll
            for (int cc = 0; cc < 4; cc++) {
#pragma unroll
                for (int it = 0; it < 4; it++) {
                    const float xa = (cc == 0) ? xv[it].x : (cc == 1) ? xv[it].y
                                   : (cc == 2) ? xv[it].z : xv[it].w;
#pragma unroll
                    for (int ie = 0; ie < 4; ie++) {
                        const float wa = (cc == 0) ? wv[ie].x : (cc == 1) ? wv[ie].y
                                       : (cc == 2) ? wv[ie].z : wv[ie].w;
                        acc[it][ie][s] = fmaf(xa, wa, acc[it][ie][s]);
                    }
                }
            }
        }
        __syncthreads();
    }

    // ---- epilogue (aliases smem; last mainloop sync covers it) ----
    float* lt    = (float*)smraw;          // [64][65]
    float* sbias = lt + 64 * 65;           // [64]
    int*   sC    = (int*)(sbias + 64);     // [64]

#pragma unroll
    for (int it = 0; it < 4; it++) {
        const int t = warpM * 32 + tg + it * 8;
#pragma unroll
        for (int ie = 0; ie < 4; ie++) {
            const int e = warpN * 16 + eg + ie * 4;
            const float p02 = acc[it][ie][0] + acc[it][ie][2];
            const float p13 = acc[it][ie][1] + acc[it][ie][3];
            lt[t * 65 + e] = p02 + p13;
        }
    }
    if (tid < NEXP) { sbias[tid] = bias[tid]; sC[tid] = 0; }
    __syncthreads();

    if (tid < TILE_M) {
        const int j = tid;
        float* row = lt + j * 65;

        float ssum = 0.0f;
#pragma unroll 8
        for (int e = 0; e < NEXP; e++) ssum += sigm(row[e]);

        unsigned long long used = 0ull;
        int   isel[KSEL];
        float bestv[KSEL + 1];
        float wsel[KSEL];
        float wsum = 0.0f;
        for (int k = 0; k < KSEL + 1; k++) {
            float best = -3.402823466e38f;
            int   bi   = 0;
            for (int e = 0; e < NEXP; e++) {
                if (!((used >> e) & 1ull)) {
                    const float bl = row[e] + sbias[e];
                    if (bl > best) { best = bl; bi = e; }
                }
            }
            used |= 1ull << bi;
            bestv[k] = best;
            if (k < KSEL) {
                isel[k] = bi;
                const float sc = sigm(row[bi]);
                wsel[k] = sc;
                wsum += sc;
            }
        }
        float minGap = 3.402823466e38f;
#pragma unroll
        for (int k = 0; k < KSEL; k++) {
            const float g = bestv[k] - bestv[k + 1];
            minGap = (g < minGap) ? g : minGap;
        }
        g_flag[m0 + j] = (minGap < TAU) ? 1 : 0;

        const float inv = 1.0f / (wsum + 1e-10f);
        float* oi = out + (size_t)(m0 + j) * KSEL;
        float* ow = out + OUT_W + (size_t)(m0 + j) * KSEL;
#pragma unroll
        for (int k = 0; k < KSEL; k++) {
            oi[k] = (float)isel[k];
            ow[k] = wsel[k] * inv;
            atomicAdd(&sC[isel[k]], 1);
        }
        const float pin = 1.0f / (ssum + 1e-10f);
        for (int e = 0; e < NEXP; e++) row[e] = sigm(row[e]) * pin;
    }
    __syncthreads();

    if (tid < NEXP) {
        float ps = 0.0f;
        for (int j = 0; j < TILE_M; j++) ps += lt[j * 65 + tid];
        g_Pp[blockIdx.x * NEXP + tid] = ps;
        g_Cp[blockIdx.x * NEXP + tid] = sC[tid];
    }
}

// ================== compaction: deterministic flagged-token list ==================
__global__ void gate_compact() {
    __shared__ int cnt[256];
    __shared__ int off[256];
    const int tid = threadIdx.x;
    const int per = NTOK / 256;    // 64
    int c = 0;
    for (int i = 0; i < per; i++) c += g_flag[tid * per + i];
    cnt[tid] = c;
    __syncthreads();
    if (tid == 0) {
        int r = 0;
        for (int i = 0; i < 256; i++) { off[i] = r; r += cnt[i]; }
        g_nflag = r;
    }
    __syncthreads();
    int o = off[tid];
    for (int i = 0; i < per; i++) {
        const int t = tid * per + i;
        if (g_flag[t]) g_list[o++] = t;
    }
}

// ================== pass 2: ensemble re-vote, one token per block ==================
__global__ __launch_bounds__(256, 1)
void gate_vote(const float* __restrict__ x,
               const float* __restrict__ w,
               const float* __restrict__ bias,
               float* __restrict__ out) {
    __shared__ float sx[HDIM];           // 8 KB
    __shared__ float swb[2][64 * 33];    // 16.9 KB, stride 33 -> conflict-free lane=e reads
    __shared__ float sL[NEXP];
    __shared__ float sb[NEXP];
    const int tid = threadIdx.x;
    if (tid < NEXP) sb[tid] = bias[tid];
    const int nf = g_nflag;

    for (int idx = blockIdx.x; idx < nf; idx += VGRID) {
        const int tok = g_list[idx];
        __syncthreads();   // protect smem reuse across list iterations
        for (int i = tid; i < HDIM; i += 256)
            sx[i] = x[(size_t)tok * HDIM + i];
        if (tid >= 128) {           // prologue: fill buffer 0 (chunk 0)
            const int p = tid - 128;
#pragma unroll
            for (int r = 0; r < 4; r++) {
                const int f4 = p + r * 128;
                const int e = f4 >> 3, q = f4 & 7;
                const float4 v = *(const float4*)(w + (size_t)e * HDIM + q * 4);
                swb[0][e * 33 + q * 4 + 0] = v.x;
                swb[0][e * 33 + q * 4 + 1] = v.y;
                swb[0][e * 33 + q * 4 + 2] = v.z;
                swb[0][e * 33 + q * 4 + 3] = v.w;
            }
        }
        __syncthreads();

        float aS = 0.0f, aH = 0.0f, aQ = 0.0f;
        float g16a = 0, g16b = 0, g16c = 0, g16d = 0;
        float g32_0 = 0, g32_1 = 0, g32_2 = 0, g32_3 = 0,
              g32_4 = 0, g32_5 = 0, g32_6 = 0, g32_7 = 0;
        float p2_0 = 0, p4_0 = 0, p4_1 = 0, p4_2 = 0;

        for (int c = 0; c < HDIM / 32; c++) {
            const int cur = c & 1;
            if (tid < 64) {
                const float* wrow = &swb[cur][tid * 33];
                const float* xrow = &sx[c * 32];
#pragma unroll
                for (int kk = 0; kk < 32; kk++) {
                    const float xa = xrow[kk];
                    const float wa = wrow[kk];
                    aS = fmaf(xa, wa, aS);
                    aH = fmaf(xa, wa, aH);
                    aQ = fmaf(xa, wa, aQ);
                    const int q = kk >> 2;
                    if ((q & 3) == 0)      g16a = fmaf(xa, wa, g16a);
                    else if ((q & 3) == 1) g16b = fmaf(xa, wa, g16b);
                    else if ((q & 3) == 2) g16c = fmaf(xa, wa, g16c);
                    else                   g16d = fmaf(xa, wa, g16d);
                    if      (q == 0) g32_0 = fmaf(xa, wa, g32_0);
                    else if (q == 1) g32_1 = fmaf(xa, wa, g32_1);
                    else if (q == 2) g32_2 = fmaf(xa, wa, g32_2);
                    else if (q == 3) g32_3 = fmaf(xa, wa, g32_3);
                    else if (q == 4) g32_4 = fmaf(xa, wa, g32_4);
                    else if (q == 5) g32_5 = fmaf(xa, wa, g32_5);
                    else if (q == 6) g32_6 = fmaf(xa, wa, g32_6);
                    else             g32_7 = fmaf(xa, wa, g32_7);
                }
                if (c == 15) { p4_0 = aQ; aQ = 0.0f; }
                if (c == 31) { p4_1 = aQ; aQ = 0.0f; p2_0 = aH; aH = 0.0f; }
                if (c == 47) { p4_2 = aQ; aQ = 0.0f; }
            } else if (tid >= 128 && c + 1 < HDIM / 32) {
                const int p = tid - 128;
#pragma unroll
                for (int r = 0; r < 4; r++) {
                    const int f4 = p + r * 128;
                    const int e = f4 >> 3, q = f4 & 7;
                    const float4 v = *(const float4*)(w + (size_t)e * HDIM + (c + 1) * 32 + q * 4);
                    swb[cur ^ 1][e * 33 + q * 4 + 0] = v.x;
                    swb[cur ^ 1][e * 33 + q * 4 + 1] = v.y;
                    swb[cur ^ 1][e * 33 + q * 4 + 2] = v.z;
                    swb[cur ^ 1][e * 33 + q * 4 + 3] = v.w;
                }
            }
            __syncthreads();
        }

        if (tid < NEXP) {
            const float L1 = aS;
            const float L2 = (g16a + g16c) + (g16b + g16d);
            const float L3 = p2_0 + aH;
            const float L4 = ((p4_0 + p4_1) + p4_2) + aQ;
            const float L5 = ((g32_0 + g32_1) + (g32_2 + g32_3))
                           + ((g32_4 + g32_5) + (g32_6 + g32_7));
            float v[5] = {L1, L2, L3, L4, L5};
#pragma unroll
            for (int a = 0; a < 4; a++)
#pragma unroll
                for (int b = 0; b < 4 - a; b++)
                    if (v[b] > v[b + 1]) { const float t = v[b]; v[b] = v[b + 1]; v[b + 1] = t; }
            sL[tid] = v[2];
        }
        __syncthreads();

        if (tid == 0) {
            unsigned long long used = 0ull;
            int   isel[KSEL];
            float wsel[KSEL];
            float wsum = 0.0f;
            for (int k = 0; k < KSEL; k++) {
                float best = -3.402823466e38f;
                int   bi   = 0;
                for (int e = 0; e < NEXP; e++) {
                    if (!((used >> e) & 1ull)) {
                        const float bl = sL[e] + sb[e];
                        if (bl > best) { best = bl; bi = e; }
                    }
                }
                used |= 1ull << bi;
                isel[k] = bi;
                const float sc = sigm(sL[bi]);
                wsel[k] = sc;
                wsum += sc;
            }
            const float inv = 1.0f / (wsum + 1e-10f);
            for (int k = 0; k < KSEL; k++) {
                out[(size_t)tok * KSEL + k]         = (float)isel[k];
                out[OUT_W + (size_t)tok * KSEL + k] = wsel[k] * inv;
            }
        }
    }
}

// ============================ pass 3: reductions ============================
__global__ void gate_final(float* __restrict__ out) {
    __shared__ float sP[NB][NEXP];
    __shared__ int   sCt[NB][NEXP];
    __shared__ float red[NEXP];
    const int tid = threadIdx.x;
    const int e = tid & 63;
    const int b = tid >> 6;      // batch 0..3
    int   cb = 0;
    float pb = 0.0f;
    const int base = b * (SEQ / TILE_M);
    for (int blk = 0; blk < SEQ / TILE_M; blk++) {
        const int g = (base + blk) * NEXP + e;
        cb += g_Cp[g];
        pb += g_Pp[g];
    }
    sCt[b][e] = cb;
    sP[b][e]  = pb;
    __syncthreads();
    if (tid < NEXP) {
        long long load = 0;
        float part = 0.0f;
        for (int bb = 0; bb < NB; bb++) {
            const int c = sCt[bb][tid];
            load += c;
            const float fi = (float)c / (float)(KSEL * SEQ);
            const float Pi = sP[bb][tid] / (float)SEQ;
            part += fi * Pi;
        }
        out[OUT_LOAD + tid] = (float)load;
        red[tid] = part;
    }
    __syncthreads();
    if (tid == 0) {
        float s = 0.0f;
        for (int i = 0; i < NEXP; i++) s += red[i];
        out[OUT_LOSS] = 0.01f * s / (float)NB;   // SEQ_ALPHA * mean over batch
    }
}

extern "C" void kernel_launch(void* const* d_in, const int* in_sizes, int n_in,
                              void* d_out, int out_size) {
    const float* x    = (const float*)d_in[0];
    const float* w    = (const float*)d_in[1];
    const float* bias = (const float*)d_in[2];
    float* out = (float*)d_out;
    (void)in_sizes; (void)n_in; (void)out_size;

    gate_main<<<NBLK, 256>>>(x, w, bias, out);
    gate_compact<<<1, 256>>>();
    gate_vote<<<VGRID, 256>>>(x, w, bias, out);
    gate_final<<<1, 256>>>(out);
}

// round 13
// speedup vs baseline: 2.0297x; 1.6328x over previous
#include <cuda_runtime.h>
#include <cuda_bf16.h>
#include <cstdint>

#define HDIM   2048
#define NEXP   64
#define KSEL   8
#define SEQ    4096
#define NB     4
#define NTOK   16384          // NB*SEQ
#define TILE_M 64
#define NBLK   (NTOK / TILE_M)   // 256 blocks
#define OUT_W    ((size_t)NTOK * KSEL)        // 131072
#define OUT_LOSS ((size_t)2 * NTOK * KSEL)    // 262144
#define OUT_LOAD (OUT_LOSS + 1)               // 262145
#define TAU    3e-5f          // near-tie threshold (bf16x3 pass-1 error ~3e-6)
#define VGRID  128
#define MSTR   72             // smem bf16 row stride: 144B -> conflict-free frags

__device__ float g_Pp[NBLK * NEXP];
__device__ int   g_Cp[NBLK * NEXP];
__device__ unsigned char g_flag[NTOK];
__device__ int   g_nflag;
__device__ int   g_list[NTOK];
__device__ __nv_bfloat16 g_whi[NEXP * HDIM];
__device__ __nv_bfloat16 g_wlo[NEXP * HDIM];

__device__ __forceinline__ float sigm(float x) {
    return 1.0f / (1.0f + expf(-x));
}

__device__ __forceinline__ uint32_t bpack(__nv_bfloat16 a, __nv_bfloat16 b) {
    __nv_bfloat162 t; t.x = a; t.y = b;
    return *(uint32_t*)&t;
}

__device__ __forceinline__ void mma16816(float* c,
                                         uint32_t a0, uint32_t a1, uint32_t a2, uint32_t a3,
                                         uint32_t b0, uint32_t b1) {
    asm volatile(
        "mma.sync.aligned.m16n8k16.row.col.f32.bf16.bf16.f32 "
        "{%0,%1,%2,%3}, {%4,%5,%6,%7}, {%8,%9}, {%0,%1,%2,%3};"
        : "+f"(c[0]), "+f"(c[1]), "+f"(c[2]), "+f"(c[3])
        : "r"(a0), "r"(a1), "r"(a2), "r"(a3), "r"(b0), "r"(b1));
}

// ---------------- w split: fp32 -> bf16 hi + bf16 lo (once) ----------------
__global__ void wcvt(const float* __restrict__ w) {
    const int stride = gridDim.x * blockDim.x;
    for (int i = blockIdx.x * blockDim.x + threadIdx.x; i < NEXP * HDIM; i += stride) {
        const float v = w[i];
        const __nv_bfloat16 hi = __float2bfloat16(v);
        g_whi[i] = hi;
        g_wlo[i] = __float2bfloat16(v - __bfloat162float(hi));
    }
}

// ============================ pass 1: GEMM + select ============================
// bf16x3 tensor-core GEMM: logits = xhi*whi + xhi*wlo + xlo*whi (fp32 acc).
__global__ __launch_bounds__(256, 2)
void gate_main(const float* __restrict__ x,
               const float* __restrict__ bias,
               float* __restrict__ out) {
    __shared__ __align__(16) unsigned char smraw[4 * TILE_M * MSTR * 2];  // 36864 B
    __nv_bfloat16* xh = (__nv_bfloat16*)smraw;      // [64][72]
    __nv_bfloat16* xl = xh + TILE_M * MSTR;
    __nv_bfloat16* wh = xl + TILE_M * MSTR;
    __nv_bfloat16* wl = wh + TILE_M * MSTR;

    const int tid  = threadIdx.x;
    const int m0   = blockIdx.x * TILE_M;
    const int warp = tid >> 5, lane = tid & 31;
    const int gid  = lane >> 2, tid4 = lane & 3;
    const int r = warp & 3;        // token row-group: 16 tokens
    const int h = warp >> 1 & 2 ? 0 : 0;  // placeholder (unused)
    const int hh = warp >> 2;      // expert col-half: 32 experts

    // staging: thread -> row (0..63), 16 consecutive cols
    const int row  = tid >> 2;
    const int colb = (tid & 3) * 16;
    const float* gx = x + (size_t)(m0 + row) * HDIM + colb;
    const __nv_bfloat16* gwh = g_whi + (size_t)row * HDIM + colb;
    const __nv_bfloat16* gwl = g_wlo + (size_t)row * HDIM + colb;

    float acc[4][4];
#pragma unroll
    for (int j = 0; j < 4; j++)
#pragma unroll
        for (int q = 0; q < 4; q++) acc[j][q] = 0.0f;

    float4 px[4];
    uint4  pwh[2], pwl[2];
#pragma unroll
    for (int q = 0; q < 4; q++) px[q] = *(const float4*)(gx + 4 * q);
    pwh[0] = *(const uint4*)(gwh);     pwh[1] = *(const uint4*)(gwh + 8);
    pwl[0] = *(const uint4*)(gwl);     pwl[1] = *(const uint4*)(gwl + 8);

    // mma frag smem index bases (element units)
    const int aR0 = (16 * r + gid) * MSTR + 2 * tid4;        // a rows gid / gid+8
    const int bC0 = (32 * hh + gid) * MSTR + 2 * tid4;       // b tile j: +8*MSTR*j

    for (int kc = 0; kc < HDIM / 64; ++kc) {
        // --- stage current chunk ---
#pragma unroll
        for (int q = 0; q < 4; q++) {
            const float4 v = px[q];
            const __nv_bfloat16 h0 = __float2bfloat16(v.x);
            const __nv_bfloat16 h1 = __float2bfloat16(v.y);
            const __nv_bfloat16 h2 = __float2bfloat16(v.z);
            const __nv_bfloat16 h3 = __float2bfloat16(v.w);
            const __nv_bfloat16 l0 = __float2bfloat16(v.x - __bfloat162float(h0));
            const __nv_bfloat16 l1 = __float2bfloat16(v.y - __bfloat162float(h1));
            const __nv_bfloat16 l2 = __float2bfloat16(v.z - __bfloat162float(h2));
            const __nv_bfloat16 l3 = __float2bfloat16(v.w - __bfloat162float(h3));
            const int o = row * MSTR + colb + 4 * q;
            *(uint2*)(xh + o) = make_uint2(bpack(h0, h1), bpack(h2, h3));
            *(uint2*)(xl + o) = make_uint2(bpack(l0, l1), bpack(l2, l3));
        }
        {
            const int o = row * MSTR + colb;
            *(uint4*)(wh + o) = pwh[0];  *(uint4*)(wh + o + 8) = pwh[1];
            *(uint4*)(wl + o) = pwl[0];  *(uint4*)(wl + o + 8) = pwl[1];
        }
        __syncthreads();
        if (kc + 1 < HDIM / 64) {
            const int k0 = (kc + 1) * 64;
#pragma unroll
            for (int q = 0; q < 4; q++) px[q] = *(const float4*)(gx + k0 + 4 * q);
            pwh[0] = *(const uint4*)(gwh + k0);  pwh[1] = *(const uint4*)(gwh + k0 + 8);
            pwl[0] = *(const uint4*)(gwl + k0);  pwl[1] = *(const uint4*)(gwl + k0 + 8);
        }
        // --- mma over 4 k16 steps ---
#pragma unroll
        for (int ks = 0; ks < 4; ks++) {
            const int k0 = ks * 16;
            const uint32_t ah0 = *(const uint32_t*)(xh + aR0 + k0);
            const uint32_t ah1 = *(const uint32_t*)(xh + aR0 + 8 * MSTR + k0);
            const uint32_t ah2 = *(const uint32_t*)(xh + aR0 + k0 + 8);
            const uint32_t ah3 = *(const uint32_t*)(xh + aR0 + 8 * MSTR + k0 + 8);
            const uint32_t al0 = *(const uint32_t*)(xl + aR0 + k0);
            const uint32_t al1 = *(const uint32_t*)(xl + aR0 + 8 * MSTR + k0);
            const uint32_t al2 = *(const uint32_t*)(xl + aR0 + k0 + 8);
            const uint32_t al3 = *(const uint32_t*)(xl + aR0 + 8 * MSTR + k0 + 8);
#pragma unroll
            for (int j = 0; j < 4; j++) {
                const int bo = bC0 + j * 8 * MSTR + k0;
                const uint32_t bh0 = *(const uint32_t*)(wh + bo);
                const uint32_t bh1 = *(const uint32_t*)(wh + bo + 8);
                const uint32_t bl0 = *(const uint32_t*)(wl + bo);
                const uint32_t bl1 = *(const uint32_t*)(wl + bo + 8);
                mma16816(acc[j], ah0, ah1, ah2, ah3, bh0, bh1);
                mma16816(acc[j], ah0, ah1, ah2, ah3, bl0, bl1);
                mma16816(acc[j], al0, al1, al2, al3, bh0, bh1);
            }
        }
        __syncthreads();
    }

    // ---- epilogue (aliases smem; last mainloop sync covers it) ----
    float* lt    = (float*)smraw;          // [64][65]
    float* sbias = lt + 64 * 65;           // [64]
    int*   sC    = (int*)(sbias + 64);     // [64]

    {
        const int t0 = 16 * r + gid;
#pragma unroll
        for (int j = 0; j < 4; j++) {
            const int e = 32 * hh + 8 * j + 2 * tid4;
            lt[t0 * 65 + e]           = acc[j][0];
            lt[t0 * 65 + e + 1]       = acc[j][1];
            lt[(t0 + 8) * 65 + e]     = acc[j][2];
            lt[(t0 + 8) * 65 + e + 1] = acc[j][3];
        }
    }
    if (tid < NEXP) { sbias[tid] = bias[tid]; sC[tid] = 0; }
    __syncthreads();

    if (tid < TILE_M) {
        const int j = tid;
        float* rowp = lt + j * 65;

        float ssum = 0.0f;
#pragma unroll 8
        for (int e = 0; e < NEXP; e++) ssum += sigm(rowp[e]);

        unsigned long long used = 0ull;
        int   isel[KSEL];
        float bestv[KSEL + 1];
        float wsel[KSEL];
        float wsum = 0.0f;
        for (int k = 0; k < KSEL + 1; k++) {
            float best = -3.402823466e38f;
            int   bi   = 0;
            for (int e = 0; e < NEXP; e++) {
                if (!((used >> e) & 1ull)) {
                    const float bl = rowp[e] + sbias[e];
                    if (bl > best) { best = bl; bi = e; }
                }
            }
            used |= 1ull << bi;
            bestv[k] = best;
            if (k < KSEL) {
                isel[k] = bi;
                const float sc = sigm(rowp[bi]);
                wsel[k] = sc;
                wsum += sc;
            }
        }
        float minGap = 3.402823466e38f;
#pragma unroll
        for (int k = 0; k < KSEL; k++) {
            const float g = bestv[k] - bestv[k + 1];
            minGap = (g < minGap) ? g : minGap;
        }
        g_flag[m0 + j] = (minGap < TAU) ? 1 : 0;

        const float inv = 1.0f / (wsum + 1e-10f);
        float* oi = out + (size_t)(m0 + j) * KSEL;
        float* ow = out + OUT_W + (size_t)(m0 + j) * KSEL;
#pragma unroll
        for (int k = 0; k < KSEL; k++) {
            oi[k] = (float)isel[k];
            ow[k] = wsel[k] * inv;
            atomicAdd(&sC[isel[k]], 1);
        }
        const float pin = 1.0f / (ssum + 1e-10f);
        for (int e = 0; e < NEXP; e++) rowp[e] = sigm(rowp[e]) * pin;
    }
    __syncthreads();

    if (tid < NEXP) {
        float ps = 0.0f;
        for (int j = 0; j < TILE_M; j++) ps += lt[j * 65 + tid];
        g_Pp[blockIdx.x * NEXP + tid] = ps;
        g_Cp[blockIdx.x * NEXP + tid] = sC[tid];
    }
}

// ================== compaction: deterministic flagged-token list ==================
__global__ void gate_compact() {
    __shared__ int cnt[256];
    __shared__ int off[256];
    const int tid = threadIdx.x;
    const int per = NTOK / 256;    // 64
    int c = 0;
    for (int i = 0; i < per; i++) c += g_flag[tid * per + i];
    cnt[tid] = c;
    __syncthreads();
    if (tid == 0) {
        int r = 0;
        for (int i = 0; i < 256; i++) { off[i] = r; r += cnt[i]; }
        g_nflag = r;
    }
    __syncthreads();
    int o = off[tid];
    for (int i = 0; i < per; i++) {
        const int t = tid * per + i;
        if (g_flag[t]) g_list[o++] = t;
    }
}

// ================== pass 2: ensemble re-vote, one token per block ==================
__global__ __launch_bounds__(256, 1)
void gate_vote(const float* __restrict__ x,
               const float* __restrict__ w,
               const float* __restrict__ bias,
               float* __restrict__ out) {
    __shared__ float sx[HDIM];           // 8 KB
    __shared__ float swb[2][64 * 33];    // 16.9 KB
    __shared__ float sL[NEXP];
    __shared__ float sb[NEXP];
    const int tid = threadIdx.x;
    if (tid < NEXP) sb[tid] = bias[tid];
    const int nf = g_nflag;

    for (int idx = blockIdx.x; idx < nf; idx += VGRID) {
        const int tok = g_list[idx];
        __syncthreads();
        for (int i = tid; i < HDIM; i += 256)
            sx[i] = x[(size_t)tok * HDIM + i];
        if (tid >= 128) {
            const int p = tid - 128;
#pragma unroll
            for (int r = 0; r < 4; r++) {
                const int f4 = p + r * 128;
                const int e = f4 >> 3, q = f4 & 7;
                const float4 v = *(const float4*)(w + (size_t)e * HDIM + q * 4);
                swb[0][e * 33 + q * 4 + 0] = v.x;
                swb[0][e * 33 + q * 4 + 1] = v.y;
                swb[0][e * 33 + q * 4 + 2] = v.z;
                swb[0][e * 33 + q * 4 + 3] = v.w;
            }
        }
        __syncthreads();

        float aS = 0.0f, aH = 0.0f, aQ = 0.0f;
        float g16a = 0, g16b = 0, g16c = 0, g16d = 0;
        float g32_0 = 0, g32_1 = 0, g32_2 = 0, g32_3 = 0,
              g32_4 = 0, g32_5 = 0, g32_6 = 0, g32_7 = 0;
        float p2_0 = 0, p4_0 = 0, p4_1 = 0, p4_2 = 0;

        for (int c = 0; c < HDIM / 32; c++) {
            const int cur = c & 1;
            if (tid < 64) {
                const float* wrow = &swb[cur][tid * 33];
                const float* xrow = &sx[c * 32];
#pragma unroll
                for (int kk = 0; kk < 32; kk++) {
                    const float xa = xrow[kk];
                    const float wa = wrow[kk];
                    aS = fmaf(xa, wa, aS);
                    aH = fmaf(xa, wa, aH);
                    aQ = fmaf(xa, wa, aQ);
                    const int q = kk >> 2;
                    if ((q & 3) == 0)      g16a = fmaf(xa, wa, g16a);
                    else if ((q & 3) == 1) g16b = fmaf(xa, wa, g16b);
                    else if ((q & 3) == 2) g16c = fmaf(xa, wa, g16c);
                    else                   g16d = fmaf(xa, wa, g16d);
                    if      (q == 0) g32_0 = fmaf(xa, wa, g32_0);
                    else if (q == 1) g32_1 = fmaf(xa, wa, g32_1);
                    else if (q == 2) g32_2 = fmaf(xa, wa, g32_2);
                    else if (q == 3) g32_3 = fmaf(xa, wa, g32_3);
                    else if (q == 4) g32_4 = fmaf(xa, wa, g32_4);
                    else if (q == 5) g32_5 = fmaf(xa, wa, g32_5);
                    else if (q == 6) g32_6 = fmaf(xa, wa, g32_6);
                    else             g32_7 = fmaf(xa, wa, g32_7);
                }
                if (c == 15) { p4_0 = aQ; aQ = 0.0f; }
                if (c == 31) { p4_1 = aQ; aQ = 0.0f; p2_0 = aH; aH = 0.0f; }
                if (c == 47) { p4_2 = aQ; aQ = 0.0f; }
            } else if (tid >= 128 && c + 1 < HDIM / 32) {
                const int p = tid - 128;
#pragma unroll
                for (int r = 0; r < 4; r++) {
                    const int f4 = p + r * 128;
                    const int e = f4 >> 3, q = f4 & 7;
                    const float4 v = *(const float4*)(w + (size_t)e * HDIM + (c + 1) * 32 + q * 4);
                    swb[cur ^ 1][e * 33 + q * 4 + 0] = v.x;
                    swb[cur ^ 1][e * 33 + q * 4 + 1] = v.y;
                    swb[cur ^ 1][e * 33 + q * 4 + 2] = v.z;
                    swb[cur ^ 1][e * 33 + q * 4 + 3] = v.w;
                }
            }
            __syncthreads();
        }

        if (tid < NEXP) {
            const float L1 = aS;
            const float L2 = (g16a + g16c) + (g16b + g16d);
            const float L3 = p2_0 + aH;
            const float L4 = ((p4_0 + p4_1) + p4_2) + aQ;
            const float L5 = ((g32_0 + g32_1) + (g32_2 + g32_3))
                           + ((g32_4 + g32_5) + (g32_6 + g32_7));
            float v[5] = {L1, L2, L3, L4, L5};
#pragma unroll
            for (int a = 0; a < 4; a++)
#pragma unroll
                for (int b = 0; b < 4 - a; b++)
                    if (v[b] > v[b + 1]) { const float t = v[b]; v[b] = v[b + 1]; v[b + 1] = t; }
            sL[tid] = v[2];
        }
        __syncthreads();

        if (tid == 0) {
            unsigned long long used = 0ull;
            int   isel[KSEL];
            float wsel[KSEL];
            float wsum = 0.0f;
            for (int k = 0; k < KSEL; k++) {
                float best = -3.402823466e38f;
                int   bi   = 0;
                for (int e = 0; e < NEXP; e++) {
                    if (!((used >> e) & 1ull)) {
                        const float bl = sL[e] + sb[e];
                        if (bl > best) { best = bl; bi = e; }
                    }
                }
                used |= 1ull << bi;
                isel[k] = bi;
                const float sc = sigm(sL[bi]);
                wsel[k] = sc;
                wsum += sc;
            }
            const float inv = 1.0f / (wsum + 1e-10f);
            for (int k = 0; k < KSEL; k++) {
                out[(size_t)tok * KSEL + k]         = (float)isel[k];
                out[OUT_W + (size_t)tok * KSEL + k] = wsel[k] * inv;
            }
        }
    }
}

// ============================ pass 3: reductions ============================
__global__ void gate_final(float* __restrict__ out) {
    __shared__ float sP[NB][NEXP];
    __shared__ int   sCt[NB][NEXP];
    __shared__ float red[NEXP];
    const int tid = threadIdx.x;
    const int e = tid & 63;
    const int b = tid >> 6;
    int   cb = 0;
    float pb = 0.0f;
    const int base = b * (SEQ / TILE_M);
    for (int blk = 0; blk < SEQ / TILE_M; blk++) {
        const int g = (base + blk) * NEXP + e;
        cb += g_Cp[g];
        pb += g_Pp[g];
    }
    sCt[b][e] = cb;
    sP[b][e]  = pb;
    __syncthreads();
    if (tid < NEXP) {
        long long load = 0;
        float part = 0.0f;
        for (int bb = 0; bb < NB; bb++) {
            const int c = sCt[bb][tid];
            load += c;
            const float fi = (float)c / (float)(KSEL * SEQ);
            const float Pi = sP[bb][tid] / (float)SEQ;
            part += fi * Pi;
        }
        out[OUT_LOAD + tid] = (float)load;
        red[tid] = part;
    }
    __syncthreads();
    if (tid == 0) {
        float s = 0.0f;
        for (int i = 0; i < NEXP; i++) s += red[i];
        out[OUT_LOSS] = 0.01f * s / (float)NB;   // SEQ_ALPHA * mean over batch
    }
}

extern "C" void kernel_launch(void* const* d_in, const int* in_sizes, int n_in,
                              void* d_out, int out_size) {
    const float* x    = (const float*)d_in[0];
    const float* w    = (const float*)d_in[1];
    const float* bias = (const float*)d_in[2];
    float* out = (float*)d_out;
    (void)in_sizes; (void)n_in; (void)out_size;

    wcvt<<<128, 256>>>(w);
    gate_main<<<NBLK, 256>>>(x, bias, out);
    gate_compact<<<1, 256>>>();
    gate_vote<<<VGRID, 256>>>(x, w, bias, out);
    gate_final<<<1, 256>>>(out);
}

// round 14
// speedup vs baseline: 2.1377x; 1.0532x over previous
#include <cuda_runtime.h>
#include <cuda_bf16.h>
#include <cstdint>

#define HDIM   2048
#define NEXP   64
#define KSEL   8
#define SEQ    4096
#define NB     4
#define NTOK   16384          // NB*SEQ
#define TILE_M 64
#define NBLK   (NTOK / TILE_M)   // 256 blocks
#define OUT_W    ((size_t)NTOK * KSEL)        // 131072
#define OUT_LOSS ((size_t)2 * NTOK * KSEL)    // 262144
#define OUT_LOAD (OUT_LOSS + 1)               // 262145
#define TAU    3e-5f          // near-tie threshold (bf16x3 pass-1 error ~3e-6)
#define VGRID  256
#define MSTR   72             // smem bf16 row stride: 144B -> conflict-free frags

__device__ float g_Pp[NBLK * NEXP];
__device__ int   g_Cp[NBLK * NEXP];
__device__ unsigned char g_flag[NTOK];
__device__ int   g_nflag;
__device__ int   g_list[NTOK];
__device__ __nv_bfloat16 g_whi[NEXP * HDIM];
__device__ __nv_bfloat16 g_wlo[NEXP * HDIM];
__device__ float g_wT[HDIM * NEXP];     // wT[k][e] = w[e][k]

__device__ __forceinline__ float sigm(float x) {
    return 1.0f / (1.0f + expf(-x));
}

__device__ __forceinline__ uint32_t bpack(__nv_bfloat16 a, __nv_bfloat16 b) {
    __nv_bfloat162 t; t.x = a; t.y = b;
    return *(uint32_t*)&t;
}

__device__ __forceinline__ uint32_t sptr(const void* p) {
    return (uint32_t)__cvta_generic_to_shared(p);
}

#define LDSM4(r0, r1, r2, r3, addr) \
    asm volatile("ldmatrix.sync.aligned.m8n8.x4.shared.b16 {%0,%1,%2,%3},[%4];" \
                 : "=r"(r0), "=r"(r1), "=r"(r2), "=r"(r3) : "r"(addr))

__device__ __forceinline__ void mma16816(float* c,
                                         uint32_t a0, uint32_t a1, uint32_t a2, uint32_t a3,
                                         uint32_t b0, uint32_t b1) {
    asm volatile(
        "mma.sync.aligned.m16n8k16.row.col.f32.bf16.bf16.f32 "
        "{%0,%1,%2,%3}, {%4,%5,%6,%7}, {%8,%9}, {%0,%1,%2,%3};"
        : "+f"(c[0]), "+f"(c[1]), "+f"(c[2]), "+f"(c[3])
        : "r"(a0), "r"(a1), "r"(a2), "r"(a3), "r"(b0), "r"(b1));
}

// ------------- w prep: bf16 hi/lo split + fp32 transpose (once) -------------
__global__ void wcvt(const float* __restrict__ w) {
    const int stride = gridDim.x * blockDim.x;
    for (int i = blockIdx.x * blockDim.x + threadIdx.x; i < NEXP * HDIM; i += stride) {
        const float v = w[i];
        const __nv_bfloat16 hi = __float2bfloat16(v);
        g_whi[i] = hi;
        g_wlo[i] = __float2bfloat16(v - __bfloat162float(hi));
        const int e = i >> 11, k = i & (HDIM - 1);
        g_wT[k * NEXP + e] = v;
    }
}

// ============================ pass 1: GEMM + select ============================
// bf16x3 tensor-core GEMM: logits = xhi*whi + xhi*wlo + xlo*whi (fp32 acc).
__global__ __launch_bounds__(256, 2)
void gate_main(const float* __restrict__ x,
               const float* __restrict__ bias,
               float* __restrict__ out) {
    __shared__ __align__(16) unsigned char smraw[4 * TILE_M * MSTR * 2];  // 36864 B
    __nv_bfloat16* xh = (__nv_bfloat16*)smraw;      // [64][72]
    __nv_bfloat16* xl = xh + TILE_M * MSTR;
    __nv_bfloat16* wh = xl + TILE_M * MSTR;
    __nv_bfloat16* wl = wh + TILE_M * MSTR;

    const int tid  = threadIdx.x;
    const int m0   = blockIdx.x * TILE_M;
    const int warp = tid >> 5, lane = tid & 31;
    const int r  = warp & 3;       // token row-group: 16 tokens
    const int hh = warp >> 2;      // expert col-half: 32 experts
    const int gid = lane >> 2, tid4 = lane & 3;

    // staging: thread -> row (0..63), 16 consecutive cols
    const int row  = tid >> 2;
    const int colb = (tid & 3) * 16;
    const float* gx = x + (size_t)(m0 + row) * HDIM + colb;
    const __nv_bfloat16* gwh = g_whi + (size_t)row * HDIM + colb;
    const __nv_bfloat16* gwl = g_wlo + (size_t)row * HDIM + colb;

    float acc[4][4];
#pragma unroll
    for (int j = 0; j < 4; j++)
#pragma unroll
        for (int q = 0; q < 4; q++) acc[j][q] = 0.0f;

    float4 px[4];
    uint4  pwh[2], pwl[2];
#pragma unroll
    for (int q = 0; q < 4; q++) px[q] = *(const float4*)(gx + 4 * q);
    pwh[0] = *(const uint4*)(gwh);     pwh[1] = *(const uint4*)(gwh + 8);
    pwl[0] = *(const uint4*)(gwl);     pwl[1] = *(const uint4*)(gwl + 8);

    // ldmatrix lane-address bases
    const int arow = 16 * r + (lane & 15);
    const int acol = (lane >> 4) * 8;
    const uint32_t aHb = sptr(xh + arow * MSTR + acol);
    const uint32_t aLb = sptr(xl + arow * MSTR + acol);
    const int brow = 32 * hh + 8 * (lane >> 4) + (lane & 7);
    const int bcol = ((lane >> 3) & 1) * 8;
    const uint32_t bH0 = sptr(wh + brow * MSTR + bcol);          // jp=0 (j=0,1)
    const uint32_t bH1 = sptr(wh + (brow + 16) * MSTR + bcol);   // jp=1 (j=2,3)
    const uint32_t bL0 = sptr(wl + brow * MSTR + bcol);
    const uint32_t bL1 = sptr(wl + (brow + 16) * MSTR + bcol);

    for (int kc = 0; kc < HDIM / 64; ++kc) {
        // --- stage current chunk ---
#pragma unroll
        for (int q = 0; q < 4; q++) {
            const float4 v = px[q];
            const __nv_bfloat16 h0 = __float2bfloat16(v.x);
            const __nv_bfloat16 h1 = __float2bfloat16(v.y);
            const __nv_bfloat16 h2 = __float2bfloat16(v.z);
            const __nv_bfloat16 h3 = __float2bfloat16(v.w);
            const __nv_bfloat16 l0 = __float2bfloat16(v.x - __bfloat162float(h0));
            const __nv_bfloat16 l1 = __float2bfloat16(v.y - __bfloat162float(h1));
            const __nv_bfloat16 l2 = __float2bfloat16(v.z - __bfloat162float(h2));
            const __nv_bfloat16 l3 = __float2bfloat16(v.w - __bfloat162float(h3));
            const int o = row * MSTR + colb + 4 * q;
            *(uint2*)(xh + o) = make_uint2(bpack(h0, h1), bpack(h2, h3));
            *(uint2*)(xl + o) = make_uint2(bpack(l0, l1), bpack(l2, l3));
        }
        {
            const int o = row * MSTR + colb;
            *(uint4*)(wh + o) = pwh[0];  *(uint4*)(wh + o + 8) = pwh[1];
            *(uint4*)(wl + o) = pwl[0];  *(uint4*)(wl + o + 8) = pwl[1];
        }
        __syncthreads();
        if (kc + 1 < HDIM / 64) {
            const int k0 = (kc + 1) * 64;
#pragma unroll
            for (int q = 0; q < 4; q++) px[q] = *(const float4*)(gx + k0 + 4 * q);
            pwh[0] = *(const uint4*)(gwh + k0);  pwh[1] = *(const uint4*)(gwh + k0 + 8);
            pwl[0] = *(const uint4*)(gwl + k0);  pwl[1] = *(const uint4*)(gwl + k0 + 8);
        }
        // --- mma over 4 k16 steps, frags via ldmatrix ---
#pragma unroll
        for (int ks = 0; ks < 4; ks++) {
            const uint32_t koff = ks * 32;   // 16 bf16 = 32 bytes
            uint32_t ah0, ah1, ah2, ah3, al0, al1, al2, al3;
            LDSM4(ah0, ah1, ah2, ah3, aHb + koff);
            LDSM4(al0, al1, al2, al3, aLb + koff);
            uint32_t h00, h01, h10, h11, h20, h21, h30, h31;
            LDSM4(h00, h01, h10, h11, bH0 + koff);   // b frags j=0, j=1 (hi)
            LDSM4(h20, h21, h30, h31, bH1 + koff);   // j=2, j=3 (hi)
            uint32_t l00, l01, l10, l11, l20, l21, l30, l31;
            LDSM4(l00, l01, l10, l11, bL0 + koff);
            LDSM4(l20, l21, l30, l31, bL1 + koff);
            // per-acc order preserved: hi*hi, hi*lo, lo*hi
            mma16816(acc[0], ah0, ah1, ah2, ah3, h00, h01);
            mma16816(acc[0], ah0, ah1, ah2, ah3, l00, l01);
            mma16816(acc[0], al0, al1, al2, al3, h00, h01);
            mma16816(acc[1], ah0, ah1, ah2, ah3, h10, h11);
            mma16816(acc[1], ah0, ah1, ah2, ah3, l10, l11);
            mma16816(acc[1], al0, al1, al2, al3, h10, h11);
            mma16816(acc[2], ah0, ah1, ah2, ah3, h20, h21);
            mma16816(acc[2], ah0, ah1, ah2, ah3, l20, l21);
            mma16816(acc[2], al0, al1, al2, al3, h20, h21);
            mma16816(acc[3], ah0, ah1, ah2, ah3, h30, h31);
            mma16816(acc[3], ah0, ah1, ah2, ah3, l30, l31);
            mma16816(acc[3], al0, al1, al2, al3, h30, h31);
        }
        __syncthreads();
    }

    // ---- epilogue (aliases smem; last mainloop sync covers it) ----
    float* lt    = (float*)smraw;          // [64][65]
    float* sbias = lt + 64 * 65;           // [64]
    int*   sC    = (int*)(sbias + 64);     // [64]

    {
        const int t0 = 16 * r + gid;
#pragma unroll
        for (int j = 0; j < 4; j++) {
            const int e = 32 * hh + 8 * j + 2 * tid4;
            lt[t0 * 65 + e]           = acc[j][0];
            lt[t0 * 65 + e + 1]       = acc[j][1];
            lt[(t0 + 8) * 65 + e]     = acc[j][2];
            lt[(t0 + 8) * 65 + e + 1] = acc[j][3];
        }
    }
    if (tid < NEXP) { sbias[tid] = bias[tid]; sC[tid] = 0; }
    __syncthreads();

    if (tid < TILE_M) {
        const int j = tid;
        float* rowp = lt + j * 65;

        float ssum = 0.0f;
#pragma unroll 8
        for (int e = 0; e < NEXP; e++) ssum += sigm(rowp[e]);

        unsigned long long used = 0ull;
        int   isel[KSEL];
        float bestv[KSEL + 1];
        float wsel[KSEL];
        float wsum = 0.0f;
        for (int k = 0; k < KSEL + 1; k++) {
            float best = -3.402823466e38f;
            int   bi   = 0;
            for (int e = 0; e < NEXP; e++) {
                if (!((used >> e) & 1ull)) {
                    const float bl = rowp[e] + sbias[e];
                    if (bl > best) { best = bl; bi = e; }
                }
            }
            used |= 1ull << bi;
            bestv[k] = best;
            if (k < KSEL) {
                isel[k] = bi;
                const float sc = sigm(rowp[bi]);
                wsel[k] = sc;
                wsum += sc;
            }
        }
        float minGap = 3.402823466e38f;
#pragma unroll
        for (int k = 0; k < KSEL; k++) {
            const float g = bestv[k] - bestv[k + 1];
            minGap = (g < minGap) ? g : minGap;
        }
        g_flag[m0 + j] = (minGap < TAU) ? 1 : 0;

        const float inv = 1.0f / (wsum + 1e-10f);
        float* oi = out + (size_t)(m0 + j) * KSEL;
        float* ow = out + OUT_W + (size_t)(m0 + j) * KSEL;
#pragma unroll
        for (int k = 0; k < KSEL; k++) {
            oi[k] = (float)isel[k];
            ow[k] = wsel[k] * inv;
            atomicAdd(&sC[isel[k]], 1);
        }
        const float pin = 1.0f / (ssum + 1e-10f);
        for (int e = 0; e < NEXP; e++) rowp[e] = sigm(rowp[e]) * pin;
    }
    __syncthreads();

    if (tid < NEXP) {
        float ps = 0.0f;
        for (int j = 0; j < TILE_M; j++) ps += lt[j * 65 + tid];
        g_Pp[blockIdx.x * NEXP + tid] = ps;
        g_Cp[blockIdx.x * NEXP + tid] = sC[tid];
    }
}

// ========== aux: flag compaction (threads 0-255) + stats reduce (256-511) ==========
__global__ void gate_aux(float* __restrict__ out) {
    __shared__ int   cnt[256];
    __shared__ int   off[256];
    __shared__ float sP[NB][NEXP];
    __shared__ int   sCt[NB][NEXP];
    __shared__ float red[NEXP];
    const int tid = threadIdx.x;

    if (tid < 256) {
        const int per = NTOK / 256;    // 64
        int c = 0;
        for (int i = 0; i < per; i++) c += g_flag[tid * per + i];
        cnt[tid] = c;
    } else {
        const int t2 = tid - 256;      // 0..255
        const int e = t2 & 63, b = t2 >> 6;
        int   cb = 0;
        float pb = 0.0f;
        const int base = b * (SEQ / TILE_M);
        for (int blk = 0; blk < SEQ / TILE_M; blk++) {
            const int g = (base + blk) * NEXP + e;
            cb += g_Cp[g];
            pb += g_Pp[g];
        }
        sCt[b][e] = cb;
        sP[b][e]  = pb;
    }
    __syncthreads();

    if (tid == 0) {
        int r = 0;
        for (int i = 0; i < 256; i++) { off[i] = r; r += cnt[i]; }
        g_nflag = r;
    }
    if (tid >= 256 && tid < 256 + NEXP) {
        const int e = tid - 256;
        long long load = 0;
        float part = 0.0f;
        for (int bb = 0; bb < NB; bb++) {
            const int c = sCt[bb][e];
            load += c;
            const float fi = (float)c / (float)(KSEL * SEQ);
            const float Pi = sP[bb][e] / (float)SEQ;
            part += fi * Pi;
        }
        out[OUT_LOAD + e] = (float)load;
        red[e] = part;
    }
    __syncthreads();

    if (tid < 256) {
        const int per = NTOK / 256;
        int o = off[tid];
        for (int i = 0; i < per; i++) {
            const int t = tid * per + i;
            if (g_flag[t]) g_list[o++] = t;
        }
    }
    if (tid == 511) {
        float s = 0.0f;
        for (int i = 0; i < NEXP; i++) s += red[i];
        out[OUT_LOSS] = 0.01f * s / (float)NB;   // SEQ_ALPHA * mean over batch
    }
}

// ================== pass 2: ensemble re-vote, one token per 64-thread block ==================
// Thread = expert. w read coalesced from g_wT (L2-hot), no mainloop barriers.
// Chains bit-identical to the R9/R12/R13 voters.
__global__ __launch_bounds__(64, 8)
void gate_vote(const float* __restrict__ x,
               const float* __restrict__ bias,
               float* __restrict__ out) {
    __shared__ float sx[HDIM];     // 8 KB
    __shared__ float sL[NEXP];
    const int tid = threadIdx.x;
    const int nf = g_nflag;

    for (int idx = blockIdx.x; idx < nf; idx += VGRID) {
        const int tok = g_list[idx];
        __syncthreads();   // protect sx/sL reuse across iterations
        {
            const float4* gx4 = (const float4*)(x + (size_t)tok * HDIM);
            float4* sx4 = (float4*)sx;
#pragma unroll
            for (int q = 0; q < 8; q++) sx4[q * 64 + tid] = gx4[q * 64 + tid];
        }
        __syncthreads();

        float aS = 0.0f, aH = 0.0f, aQ = 0.0f;
        float g16a = 0, g16b = 0, g16c = 0, g16d = 0;
        float g32_0 = 0, g32_1 = 0, g32_2 = 0, g32_3 = 0,
              g32_4 = 0, g32_5 = 0, g32_6 = 0, g32_7 = 0;
        float p2_0 = 0, p4_0 = 0, p4_1 = 0, p4_2 = 0;

        for (int c = 0; c < HDIM / 32; c++) {
#pragma unroll
            for (int kk = 0; kk < 32; kk++) {
                const float xa = sx[c * 32 + kk];
                const float wa = __ldg(&g_wT[(c * 32 + kk) * NEXP + tid]);
                aS = fmaf(xa, wa, aS);
                aH = fmaf(xa, wa, aH);
                aQ = fmaf(xa, wa, aQ);
                const int q = kk >> 2;
                if ((q & 3) == 0)      g16a = fmaf(xa, wa, g16a);
                else if ((q & 3) == 1) g16b = fmaf(xa, wa, g16b);
                else if ((q & 3) == 2) g16c = fmaf(xa, wa, g16c);
                else                   g16d = fmaf(xa, wa, g16d);
                if      (q == 0) g32_0 = fmaf(xa, wa, g32_0);
                else if (q == 1) g32_1 = fmaf(xa, wa, g32_1);
                else if (q == 2) g32_2 = fmaf(xa, wa, g32_2);
                else if (q == 3) g32_3 = fmaf(xa, wa, g32_3);
                else if (q == 4) g32_4 = fmaf(xa, wa, g32_4);
                else if (q == 5) g32_5 = fmaf(xa, wa, g32_5);
                else if (q == 6) g32_6 = fmaf(xa, wa, g32_6);
                else             g32_7 = fmaf(xa, wa, g32_7);
            }
            if (c == 15) { p4_0 = aQ; aQ = 0.0f; }
            if (c == 31) { p4_1 = aQ; aQ = 0.0f; p2_0 = aH; aH = 0.0f; }
            if (c == 47) { p4_2 = aQ; aQ = 0.0f; }
        }

        {
            const float L1 = aS;
            const float L2 = (g16a + g16c) + (g16b + g16d);
            const float L3 = p2_0 + aH;
            const float L4 = ((p4_0 + p4_1) + p4_2) + aQ;
            const float L5 = ((g32_0 + g32_1) + (g32_2 + g32_3))
                           + ((g32_4 + g32_5) + (g32_6 + g32_7));
            float v[5] = {L1, L2, L3, L4, L5};
#pragma unroll
            for (int a = 0; a < 4; a++)
#pragma unroll
                for (int b = 0; b < 4 - a; b++)
                    if (v[b] > v[b + 1]) { const float t = v[b]; v[b] = v[b + 1]; v[b + 1] = t; }
            sL[tid] = v[2];
        }
        __syncthreads();

        if (tid == 0) {
            unsigned long long used = 0ull;
            int   isel[KSEL];
            float wsel[KSEL];
            float wsum = 0.0f;
            for (int k = 0; k < KSEL; k++) {
                float best = -3.402823466e38f;
                int   bi   = 0;
                for (int e = 0; e < NEXP; e++) {
                    if (!((used >> e) & 1ull)) {
                        const float bl = sL[e] + __ldg(bias + e);
                        if (bl > best) { best = bl; bi = e; }
                    }
                }
                used |= 1ull << bi;
                isel[k] = bi;
                const float sc = sigm(sL[bi]);
                wsel[k] = sc;
                wsum += sc;
            }
            const float inv = 1.0f / (wsum + 1e-10f);
            for (int k = 0; k < KSEL; k++) {
                out[(size_t)tok * KSEL + k]         = (float)isel[k];
                out[OUT_W + (size_t)tok * KSEL + k] = wsel[k] * inv;
            }
        }
    }
}

extern "C" void kernel_launch(void* const* d_in, const int* in_sizes, int n_in,
                              void* d_out, int out_size) {
    const float* x    = (const float*)d_in[0];
    const float* w    = (const float*)d_in[1];
    const float* bias = (const float*)d_in[2];
    float* out = (float*)d_out;
    (void)in_sizes; (void)n_in; (void)out_size;

    wcvt<<<128, 256>>>(w);
    gate_main<<<NBLK, 256>>>(x, bias, out);
    gate_aux<<<1, 512>>>(out);
    gate_vote<<<VGRID, 64>>>(x, bias, out);
}

// round 16
// speedup vs baseline: 2.3657x; 1.1067x over previous
#include <cuda_runtime.h>
#include <cuda_bf16.h>
#include <cstdint>

#define HDIM   2048
#define NEXP   64
#define KSEL   8
#define SEQ    4096
#define NB     4
#define NTOK   16384          // NB*SEQ
#define TILE_M 64
#define NBLK   (NTOK / TILE_M)   // 256 blocks
#define OUT_W    ((size_t)NTOK * KSEL)        // 131072
#define OUT_LOSS ((size_t)2 * NTOK * KSEL)    // 262144
#define OUT_LOAD (OUT_LOSS + 1)               // 262145
#define TAU    3e-5f          // near-tie threshold (bf16x3 pass-1 error ~3e-6)
#define VGRID  256
#define MSTR   72             // smem bf16 row stride: 144B -> conflict-free frags

__device__ float g_Pp[NBLK * NEXP];
__device__ int   g_Cp[NBLK * NEXP];
__device__ unsigned char g_flag[NTOK];
__device__ int   g_nflag;
__device__ int   g_list[NTOK];
__device__ __nv_bfloat16 g_whi[NEXP * HDIM];
__device__ __nv_bfloat16 g_wlo[NEXP * HDIM];
__device__ float g_wT[HDIM * NEXP];     // wT[k][e] = w[e][k]

__device__ __forceinline__ float sigm(float x) {
    return 1.0f / (1.0f + expf(-x));
}

__device__ __forceinline__ uint32_t bpack(__nv_bfloat16 a, __nv_bfloat16 b) {
    __nv_bfloat162 t; t.x = a; t.y = b;
    return *(uint32_t*)&t;
}

__device__ __forceinline__ uint32_t sptr(const void* p) {
    return (uint32_t)__cvta_generic_to_shared(p);
}

#define LDSM4(r0, r1, r2, r3, addr) \
    asm volatile("ldmatrix.sync.aligned.m8n8.x4.shared.b16 {%0,%1,%2,%3},[%4];" \
                 : "=r"(r0), "=r"(r1), "=r"(r2), "=r"(r3) : "r"(addr))

__device__ __forceinline__ void mma16816(float* c,
                                         uint32_t a0, uint32_t a1, uint32_t a2, uint32_t a3,
                                         uint32_t b0, uint32_t b1) {
    asm volatile(
        "mma.sync.aligned.m16n8k16.row.col.f32.bf16.bf16.f32 "
        "{%0,%1,%2,%3}, {%4,%5,%6,%7}, {%8,%9}, {%0,%1,%2,%3};"
        : "+f"(c[0]), "+f"(c[1]), "+f"(c[2]), "+f"(c[3])
        : "r"(a0), "r"(a1), "r"(a2), "r"(a3), "r"(b0), "r"(b1));
}

// ------------- w prep: bf16 hi/lo split + fp32 transpose (once) -------------
__global__ void wcvt(const float* __restrict__ w) {
    const int stride = gridDim.x * blockDim.x;
    for (int i = blockIdx.x * blockDim.x + threadIdx.x; i < NEXP * HDIM; i += stride) {
        const float v = w[i];
        const __nv_bfloat16 hi = __float2bfloat16(v);
        g_whi[i] = hi;
        g_wlo[i] = __float2bfloat16(v - __bfloat162float(hi));
        const int e = i >> 11, k = i & (HDIM - 1);
        g_wT[k * NEXP + e] = v;
    }
}

// ============================ pass 1: GEMM + select ============================
// bf16x3 tensor-core GEMM: logits = xhi*whi + xhi*wlo + xlo*whi (fp32 acc).
__global__ __launch_bounds__(256, 2)
void gate_main(const float* __restrict__ x,
               const float* __restrict__ bias,
               float* __restrict__ out) {
    __shared__ __align__(16) unsigned char smraw[4 * TILE_M * MSTR * 2];  // 36864 B
    __nv_bfloat16* xh = (__nv_bfloat16*)smraw;      // [64][72]
    __nv_bfloat16* xl = xh + TILE_M * MSTR;
    __nv_bfloat16* wh = xl + TILE_M * MSTR;
    __nv_bfloat16* wl = wh + TILE_M * MSTR;

    const int tid  = threadIdx.x;
    const int m0   = blockIdx.x * TILE_M;
    const int warp = tid >> 5, lane = tid & 31;
    const int r  = warp & 3;       // token row-group: 16 tokens
    const int hh = warp >> 2;      // expert col-half: 32 experts
    const int gid = lane >> 2, tid4 = lane & 3;

    // staging: thread -> row (0..63), 16 consecutive cols
    const int row  = tid >> 2;
    const int colb = (tid & 3) * 16;
    const float* gx = x + (size_t)(m0 + row) * HDIM + colb;
    const __nv_bfloat16* gwh = g_whi + (size_t)row * HDIM + colb;
    const __nv_bfloat16* gwl = g_wlo + (size_t)row * HDIM + colb;

    float acc[4][4];
#pragma unroll
    for (int j = 0; j < 4; j++)
#pragma unroll
        for (int q = 0; q < 4; q++) acc[j][q] = 0.0f;

    float4 px[4];
    uint4  pwh[2], pwl[2];
#pragma unroll
    for (int q = 0; q < 4; q++) px[q] = *(const float4*)(gx + 4 * q);
    pwh[0] = *(const uint4*)(gwh);     pwh[1] = *(const uint4*)(gwh + 8);
    pwl[0] = *(const uint4*)(gwl);     pwl[1] = *(const uint4*)(gwl + 8);

    // ldmatrix lane-address bases
    const int arow = 16 * r + (lane & 15);
    const int acol = (lane >> 4) * 8;
    const uint32_t aHb = sptr(xh + arow * MSTR + acol);
    const uint32_t aLb = sptr(xl + arow * MSTR + acol);
    const int brow = 32 * hh + 8 * (lane >> 4) + (lane & 7);
    const int bcol = ((lane >> 3) & 1) * 8;
    const uint32_t bH0 = sptr(wh + brow * MSTR + bcol);          // jp=0 (j=0,1)
    const uint32_t bH1 = sptr(wh + (brow + 16) * MSTR + bcol);   // jp=1 (j=2,3)
    const uint32_t bL0 = sptr(wl + brow * MSTR + bcol);
    const uint32_t bL1 = sptr(wl + (brow + 16) * MSTR + bcol);

    for (int kc = 0; kc < HDIM / 64; ++kc) {
        // --- stage current chunk ---
#pragma unroll
        for (int q = 0; q < 4; q++) {
            const float4 v = px[q];
            const __nv_bfloat16 h0 = __float2bfloat16(v.x);
            const __nv_bfloat16 h1 = __float2bfloat16(v.y);
            const __nv_bfloat16 h2 = __float2bfloat16(v.z);
            const __nv_bfloat16 h3 = __float2bfloat16(v.w);
            const __nv_bfloat16 l0 = __float2bfloat16(v.x - __bfloat162float(h0));
            const __nv_bfloat16 l1 = __float2bfloat16(v.y - __bfloat162float(h1));
            const __nv_bfloat16 l2 = __float2bfloat16(v.z - __bfloat162float(h2));
            const __nv_bfloat16 l3 = __float2bfloat16(v.w - __bfloat162float(h3));
            const int o = row * MSTR + colb + 4 * q;
            *(uint2*)(xh + o) = make_uint2(bpack(h0, h1), bpack(h2, h3));
            *(uint2*)(xl + o) = make_uint2(bpack(l0, l1), bpack(l2, l3));
        }
        {
            const int o = row * MSTR + colb;
            *(uint4*)(wh + o) = pwh[0];  *(uint4*)(wh + o + 8) = pwh[1];
            *(uint4*)(wl + o) = pwl[0];  *(uint4*)(wl + o + 8) = pwl[1];
        }
        __syncthreads();
        if (kc + 1 < HDIM / 64) {
            const int k0 = (kc + 1) * 64;
#pragma unroll
            for (int q = 0; q < 4; q++) px[q] = *(const float4*)(gx + k0 + 4 * q);
            pwh[0] = *(const uint4*)(gwh + k0);  pwh[1] = *(const uint4*)(gwh + k0 + 8);
            pwl[0] = *(const uint4*)(gwl + k0);  pwl[1] = *(const uint4*)(gwl + k0 + 8);
        }
        // --- mma over 4 k16 steps, frags via ldmatrix ---
#pragma unroll
        for (int ks = 0; ks < 4; ks++) {
            const uint32_t koff = ks * 32;   // 16 bf16 = 32 bytes
            uint32_t ah0, ah1, ah2, ah3, al0, al1, al2, al3;
            LDSM4(ah0, ah1, ah2, ah3, aHb + koff);
            LDSM4(al0, al1, al2, al3, aLb + koff);
            uint32_t h00, h01, h10, h11, h20, h21, h30, h31;
            LDSM4(h00, h01, h10, h11, bH0 + koff);   // b frags j=0, j=1 (hi)
            LDSM4(h20, h21, h30, h31, bH1 + koff);   // j=2, j=3 (hi)
            uint32_t l00, l01, l10, l11, l20, l21, l30, l31;
            LDSM4(l00, l01, l10, l11, bL0 + koff);
            LDSM4(l20, l21, l30, l31, bL1 + koff);
            // per-acc order preserved: hi*hi, hi*lo, lo*hi
            mma16816(acc[0], ah0, ah1, ah2, ah3, h00, h01);
            mma16816(acc[0], ah0, ah1, ah2, ah3, l00, l01);
            mma16816(acc[0], al0, al1, al2, al3, h00, h01);
            mma16816(acc[1], ah0, ah1, ah2, ah3, h10, h11);
            mma16816(acc[1], ah0, ah1, ah2, ah3, l10, l11);
            mma16816(acc[1], al0, al1, al2, al3, h10, h11);
            mma16816(acc[2], ah0, ah1, ah2, ah3, h20, h21);
            mma16816(acc[2], ah0, ah1, ah2, ah3, l20, l21);
            mma16816(acc[2], al0, al1, al2, al3, h20, h21);
            mma16816(acc[3], ah0, ah1, ah2, ah3, h30, h31);
            mma16816(acc[3], ah0, ah1, ah2, ah3, l30, l31);
            mma16816(acc[3], al0, al1, al2, al3, h30, h31);
        }
        __syncthreads();
    }

    // ---- epilogue (aliases smem; last mainloop sync covers it) ----
    float* lt    = (float*)smraw;          // [64][65]
    float* sbias = lt + 64 * 65;           // [64]
    int*   sC    = (int*)(sbias + 64);     // [64]

    {
        const int t0 = 16 * r + gid;
#pragma unroll
        for (int j = 0; j < 4; j++) {
            const int e = 32 * hh + 8 * j + 2 * tid4;
            lt[t0 * 65 + e]           = acc[j][0];
            lt[t0 * 65 + e + 1]       = acc[j][1];
            lt[(t0 + 8) * 65 + e]     = acc[j][2];
            lt[(t0 + 8) * 65 + e + 1] = acc[j][3];
        }
    }
    if (tid < NEXP) { sbias[tid] = bias[tid]; sC[tid] = 0; }
    __syncthreads();

    if (tid < TILE_M) {
        const int j = tid;
        float* rowp = lt + j * 65;

        float ssum = 0.0f;
#pragma unroll 8
        for (int e = 0; e < NEXP; e++) ssum += sigm(rowp[e]);

        unsigned long long used = 0ull;
        int   isel[KSEL];
        float bestv[KSEL + 1];
        float wsel[KSEL];
        float wsum = 0.0f;
        for (int k = 0; k < KSEL + 1; k++) {
            float best = -3.402823466e38f;
            int   bi   = 0;
            for (int e = 0; e < NEXP; e++) {
                if (!((used >> e) & 1ull)) {
                    const float bl = rowp[e] + sbias[e];
                    if (bl > best) { best = bl; bi = e; }
                }
            }
            used |= 1ull << bi;
            bestv[k] = best;
            if (k < KSEL) {
                isel[k] = bi;
                const float sc = sigm(rowp[bi]);
                wsel[k] = sc;
                wsum += sc;
            }
        }
        float minGap = 3.402823466e38f;
#pragma unroll
        for (int k = 0; k < KSEL; k++) {
            const float g = bestv[k] - bestv[k + 1];
            minGap = (g < minGap) ? g : minGap;
        }
        g_flag[m0 + j] = (minGap < TAU) ? 1 : 0;

        const float inv = 1.0f / (wsum + 1e-10f);
        float* oi = out + (size_t)(m0 + j) * KSEL;
        float* ow = out + OUT_W + (size_t)(m0 + j) * KSEL;
#pragma unroll
        for (int k = 0; k < KSEL; k++) {
            oi[k] = (float)isel[k];
            ow[k] = wsel[k] * inv;
            atomicAdd(&sC[isel[k]], 1);
        }
        const float pin = 1.0f / (ssum + 1e-10f);
        for (int e = 0; e < NEXP; e++) rowp[e] = sigm(rowp[e]) * pin;
    }
    __syncthreads();

    if (tid < NEXP) {
        float ps = 0.0f;
        for (int j = 0; j < TILE_M; j++) ps += lt[j * 65 + tid];
        g_Pp[blockIdx.x * NEXP + tid] = ps;
        g_Cp[blockIdx.x * NEXP + tid] = sC[tid];
    }
}

// ========== aux: flag compaction (threads 0-255) + stats reduce (256-511) ==========
__global__ void gate_aux(float* __restrict__ out) {
    __shared__ int   cnt[256];
    __shared__ int   off[256];
    __shared__ float sP[NB][NEXP];
    __shared__ int   sCt[NB][NEXP];
    __shared__ float red[NEXP];
    const int tid = threadIdx.x;

    if (tid < 256) {
        const int per = NTOK / 256;    // 64
        int c = 0;
        for (int i = 0; i < per; i++) c += g_flag[tid * per + i];
        cnt[tid] = c;
    } else {
        const int t2 = tid - 256;      // 0..255
        const int e = t2 & 63, b = t2 >> 6;
        int   cb = 0;
        float pb = 0.0f;
        const int base = b * (SEQ / TILE_M);
        for (int blk = 0; blk < SEQ / TILE_M; blk++) {
            const int g = (base + blk) * NEXP + e;
            cb += g_Cp[g];
            pb += g_Pp[g];
        }
        sCt[b][e] = cb;
        sP[b][e]  = pb;
    }
    __syncthreads();

    if (tid == 0) {
        int r = 0;
        for (int i = 0; i < 256; i++) { off[i] = r; r += cnt[i]; }
        g_nflag = r;
    }
    if (tid >= 256 && tid < 256 + NEXP) {
        const int e = tid - 256;
        long long load = 0;
        float part = 0.0f;
        for (int bb = 0; bb < NB; bb++) {
            const int c = sCt[bb][e];
            load += c;
            const float fi = (float)c / (float)(KSEL * SEQ);
            const float Pi = sP[bb][e] / (float)SEQ;
            part += fi * Pi;
        }
        out[OUT_LOAD + e] = (float)load;
        red[e] = part;
    }
    __syncthreads();

    if (tid < 256) {
        const int per = NTOK / 256;
        int o = off[tid];
        for (int i = 0; i < per; i++) {
            const int t = tid * per + i;
            if (g_flag[t]) g_list[o++] = t;
        }
    }
    if (tid == 511) {
        float s = 0.0f;
        for (int i = 0; i < NEXP; i++) s += red[i];
        out[OUT_LOSS] = 0.01f * s / (float)NB;   // SEQ_ALPHA * mean over batch
    }
}

// ===== pass 2: ensemble re-vote; register-prefetched w stream, chains unchanged =====
__global__ __launch_bounds__(64, 4)
void gate_vote(const float* __restrict__ x,
               const float* __restrict__ bias,
               float* __restrict__ out) {
    __shared__ float sx[HDIM];     // 8 KB
    __shared__ float sL[NEXP];
    const int tid = threadIdx.x;
    const int nf = g_nflag;

    for (int idx = blockIdx.x; idx < nf; idx += VGRID) {
        const int tok = g_list[idx];
        __syncthreads();   // protect sx/sL reuse across iterations
        {
            const float4* gx4 = (const float4*)(x + (size_t)tok * HDIM);
            float4* sx4 = (float4*)sx;
#pragma unroll
            for (int q = 0; q < 8; q++) sx4[q * 64 + tid] = gx4[q * 64 + tid];
        }
        __syncthreads();

        const float* wcol = g_wT + tid;
        float wbuf[2][32];
#pragma unroll
        for (int kk = 0; kk < 32; kk++) wbuf[0][kk] = __ldg(wcol + kk * NEXP);

        float aS = 0.0f, aH = 0.0f, aQ = 0.0f;
        float g16a = 0, g16b = 0, g16c = 0, g16d = 0;
        float g32_0 = 0, g32_1 = 0, g32_2 = 0, g32_3 = 0,
              g32_4 = 0, g32_5 = 0, g32_6 = 0, g32_7 = 0;
        float p2_0 = 0, p4_0 = 0, p4_1 = 0, p4_2 = 0;

#pragma unroll 2
        for (int c = 0; c < HDIM / 32; c++) {
            const int cur = c & 1;
            if (c + 1 < HDIM / 32) {
#pragma unroll
                for (int kk = 0; kk < 32; kk++)
                    wbuf[cur ^ 1][kk] = __ldg(wcol + ((c + 1) * 32 + kk) * NEXP);
            }
#pragma unroll
            for (int kk = 0; kk < 32; kk++) {
                const float xa = sx[c * 32 + kk];
                const float wa = wbuf[cur][kk];
                aS = fmaf(xa, wa, aS);
                aH = fmaf(xa, wa, aH);
                aQ = fmaf(xa, wa, aQ);
                const int q = kk >> 2;
                if ((q & 3) == 0)      g16a = fmaf(xa, wa, g16a);
                else if ((q & 3) == 1) g16b = fmaf(xa, wa, g16b);
                else if ((q & 3) == 2) g16c = fmaf(xa, wa, g16c);
                else                   g16d = fmaf(xa, wa, g16d);
                if      (q == 0) g32_0 = fmaf(xa, wa, g32_0);
                else if (q == 1) g32_1 = fmaf(xa, wa, g32_1);
                else if (q == 2) g32_2 = fmaf(xa, wa, g32_2);
                else if (q == 3) g32_3 = fmaf(xa, wa, g32_3);
                else if (q == 4) g32_4 = fmaf(xa, wa, g32_4);
                else if (q == 5) g32_5 = fmaf(xa, wa, g32_5);
                else if (q == 6) g32_6 = fmaf(xa, wa, g32_6);
                else             g32_7 = fmaf(xa, wa, g32_7);
            }
            if (c == 15) { p4_0 = aQ; aQ = 0.0f; }
            if (c == 31) { p4_1 = aQ; aQ = 0.0f; p2_0 = aH; aH = 0.0f; }
            if (c == 47) { p4_2 = aQ; aQ = 0.0f; }
        }

        {
            const float L1 = aS;
            const float L2 = (g16a + g16c) + (g16b + g16d);
            const float L3 = p2_0 + aH;
            const float L4 = ((p4_0 + p4_1) + p4_2) + aQ;
            const float L5 = ((g32_0 + g32_1) + (g32_2 + g32_3))
                           + ((g32_4 + g32_5) + (g32_6 + g32_7));
            float v[5] = {L1, L2, L3, L4, L5};
#pragma unroll
            for (int a = 0; a < 4; a++)
#pragma unroll
                for (int b = 0; b < 4 - a; b++)
                    if (v[b] > v[b + 1]) { const float t = v[b]; v[b] = v[b + 1]; v[b + 1] = t; }
            sL[tid] = v[2];
        }
        __syncthreads();

        if (tid == 0) {
            unsigned long long used = 0ull;
            int   isel[KSEL];
            float wsel[KSEL];
            float wsum = 0.0f;
            for (int k = 0; k < KSEL; k++) {
                float best = -3.402823466e38f;
                int   bi   = 0;
                for (int e = 0; e < NEXP; e++) {
                    if (!((used >> e) & 1ull)) {
                        const float bl = sL[e] + __ldg(bias + e);
                        if (bl > best) { best = bl; bi = e; }
                    }
                }
                used |= 1ull << bi;
                isel[k] = bi;
                const float sc = sigm(sL[bi]);
                wsel[k] = sc;
                wsum += sc;
            }
            const float inv = 1.0f / (wsum + 1e-10f);
            for (int k = 0; k < KSEL; k++) {
                out[(size_t)tok * KSEL + k]         = (float)isel[k];
                out[OUT_W + (size_t)tok * KSEL + k] = wsel[k] * inv;
            }
        }
    }
}

extern "C" void kernel_launch(void* const* d_in, const int* in_sizes, int n_in,
                              void* d_out, int out_size) {
    const float* x    = (const float*)d_in[0];
    const float* w    = (const float*)d_in[1];
    const float* bias = (const float*)d_in[2];
    float* out = (float*)d_out;
    (void)in_sizes; (void)n_in; (void)out_size;

    wcvt<<<128, 256>>>(w);
    gate_main<<<NBLK, 256>>>(x, bias, out);
    gate_aux<<<1, 512>>>(out);
    gate_vote<<<VGRID, 64>>>(x, bias, out);
}

// round 17
// speedup vs baseline: 2.6163x; 1.1059x over previous
#include <cuda_runtime.h>
#include <cuda_bf16.h>
#include <cstdint>

#define HDIM   2048
#define NEXP   64
#define KSEL   8
#define SEQ    4096
#define NB     4
#define NTOK   16384          // NB*SEQ
#define TILE_M 64
#define NBLK   (NTOK / TILE_M)   // 256 blocks
#define OUT_W    ((size_t)NTOK * KSEL)        // 131072
#define OUT_LOSS ((size_t)2 * NTOK * KSEL)    // 262144
#define OUT_LOAD (OUT_LOSS + 1)               // 262145
#define TAU    3e-5f          // near-tie threshold (bf16x3 pass-1 error ~3e-6)
#define VGRID  256
#define MSTR   72             // smem bf16 row stride: 144B -> conflict-free frags

__device__ float g_Pp[NBLK * NEXP];
__device__ int   g_Cp[NBLK * NEXP];
__device__ unsigned char g_flag[NTOK];
__device__ int   g_nflag;
__device__ int   g_list[NTOK];
__device__ __nv_bfloat16 g_whi[NEXP * HDIM];
__device__ __nv_bfloat16 g_wlo[NEXP * HDIM];
__device__ float g_wT[HDIM * NEXP];     // wT[k][e] = w[e][k]

__device__ __forceinline__ float sigm(float x) {
    return 1.0f / (1.0f + expf(-x));
}

__device__ __forceinline__ uint32_t bpack(__nv_bfloat16 a, __nv_bfloat16 b) {
    __nv_bfloat162 t; t.x = a; t.y = b;
    return *(uint32_t*)&t;
}

__device__ __forceinline__ uint32_t sptr(const void* p) {
    return (uint32_t)__cvta_generic_to_shared(p);
}

#define LDSM4(r0, r1, r2, r3, addr) \
    asm volatile("ldmatrix.sync.aligned.m8n8.x4.shared.b16 {%0,%1,%2,%3},[%4];" \
                 : "=r"(r0), "=r"(r1), "=r"(r2), "=r"(r3) : "r"(addr))

#define CPASYNC16(saddr, gptr) \
    asm volatile("cp.async.ca.shared.global [%0], [%1], 16;" :: "r"(saddr), "l"(gptr) : "memory")
#define CP_COMMIT() asm volatile("cp.async.commit_group;" ::: "memory")
#define CP_WAIT2()  asm volatile("cp.async.wait_group 2;" ::: "memory")
#define CP_WAIT0()  asm volatile("cp.async.wait_group 0;" ::: "memory")

__device__ __forceinline__ void mma16816(float* c,
                                         uint32_t a0, uint32_t a1, uint32_t a2, uint32_t a3,
                                         uint32_t b0, uint32_t b1) {
    asm volatile(
        "mma.sync.aligned.m16n8k16.row.col.f32.bf16.bf16.f32 "
        "{%0,%1,%2,%3}, {%4,%5,%6,%7}, {%8,%9}, {%0,%1,%2,%3};"
        : "+f"(c[0]), "+f"(c[1]), "+f"(c[2]), "+f"(c[3])
        : "r"(a0), "r"(a1), "r"(a2), "r"(a3), "r"(b0), "r"(b1));
}

// ------------- w prep: bf16 hi/lo split + fp32 transpose (once) -------------
__global__ void wcvt(const float* __restrict__ w) {
    const int stride = gridDim.x * blockDim.x;
    for (int i = blockIdx.x * blockDim.x + threadIdx.x; i < NEXP * HDIM; i += stride) {
        const float v = w[i];
        const __nv_bfloat16 hi = __float2bfloat16(v);
        g_whi[i] = hi;
        g_wlo[i] = __float2bfloat16(v - __bfloat162float(hi));
        const int e = i >> 11, k = i & (HDIM - 1);
        g_wT[k * NEXP + e] = v;
    }
}

// ============================ pass 1: GEMM + select ============================
// bf16x3 tensor-core GEMM: logits = xhi*whi + xhi*wlo + xlo*whi (fp32 acc).
// (verbatim from R16 — logits bitwise stable)
__global__ __launch_bounds__(256, 2)
void gate_main(const float* __restrict__ x,
               const float* __restrict__ bias,
               float* __restrict__ out) {
    __shared__ __align__(16) unsigned char smraw[4 * TILE_M * MSTR * 2];  // 36864 B
    __nv_bfloat16* xh = (__nv_bfloat16*)smraw;      // [64][72]
    __nv_bfloat16* xl = xh + TILE_M * MSTR;
    __nv_bfloat16* wh = xl + TILE_M * MSTR;
    __nv_bfloat16* wl = wh + TILE_M * MSTR;

    const int tid  = threadIdx.x;
    const int m0   = blockIdx.x * TILE_M;
    const int warp = tid >> 5, lane = tid & 31;
    const int r  = warp & 3;       // token row-group: 16 tokens
    const int hh = warp >> 2;      // expert col-half: 32 experts
    const int gid = lane >> 2, tid4 = lane & 3;

    const int row  = tid >> 2;
    const int colb = (tid & 3) * 16;
    const float* gx = x + (size_t)(m0 + row) * HDIM + colb;
    const __nv_bfloat16* gwh = g_whi + (size_t)row * HDIM + colb;
    const __nv_bfloat16* gwl = g_wlo + (size_t)row * HDIM + colb;

    float acc[4][4];
#pragma unroll
    for (int j = 0; j < 4; j++)
#pragma unroll
        for (int q = 0; q < 4; q++) acc[j][q] = 0.0f;

    float4 px[4];
    uint4  pwh[2], pwl[2];
#pragma unroll
    for (int q = 0; q < 4; q++) px[q] = *(const float4*)(gx + 4 * q);
    pwh[0] = *(const uint4*)(gwh);     pwh[1] = *(const uint4*)(gwh + 8);
    pwl[0] = *(const uint4*)(gwl);     pwl[1] = *(const uint4*)(gwl + 8);

    const int arow = 16 * r + (lane & 15);
    const int acol = (lane >> 4) * 8;
    const uint32_t aHb = sptr(xh + arow * MSTR + acol);
    const uint32_t aLb = sptr(xl + arow * MSTR + acol);
    const int brow = 32 * hh + 8 * (lane >> 4) + (lane & 7);
    const int bcol = ((lane >> 3) & 1) * 8;
    const uint32_t bH0 = sptr(wh + brow * MSTR + bcol);
    const uint32_t bH1 = sptr(wh + (brow + 16) * MSTR + bcol);
    const uint32_t bL0 = sptr(wl + brow * MSTR + bcol);
    const uint32_t bL1 = sptr(wl + (brow + 16) * MSTR + bcol);

    for (int kc = 0; kc < HDIM / 64; ++kc) {
#pragma unroll
        for (int q = 0; q < 4; q++) {
            const float4 v = px[q];
            const __nv_bfloat16 h0 = __float2bfloat16(v.x);
            const __nv_bfloat16 h1 = __float2bfloat16(v.y);
            const __nv_bfloat16 h2 = __float2bfloat16(v.z);
            const __nv_bfloat16 h3 = __float2bfloat16(v.w);
            const __nv_bfloat16 l0 = __float2bfloat16(v.x - __bfloat162float(h0));
            const __nv_bfloat16 l1 = __float2bfloat16(v.y - __bfloat162float(h1));
            const __nv_bfloat16 l2 = __float2bfloat16(v.z - __bfloat162float(h2));
            const __nv_bfloat16 l3 = __float2bfloat16(v.w - __bfloat162float(h3));
            const int o = row * MSTR + colb + 4 * q;
            *(uint2*)(xh + o) = make_uint2(bpack(h0, h1), bpack(h2, h3));
            *(uint2*)(xl + o) = make_uint2(bpack(l0, l1), bpack(l2, l3));
        }
        {
            const int o = row * MSTR + colb;
            *(uint4*)(wh + o) = pwh[0];  *(uint4*)(wh + o + 8) = pwh[1];
            *(uint4*)(wl + o) = pwl[0];  *(uint4*)(wl + o + 8) = pwl[1];
        }
        __syncthreads();
        if (kc + 1 < HDIM / 64) {
            const int k0 = (kc + 1) * 64;
#pragma unroll
            for (int q = 0; q < 4; q++) px[q] = *(const float4*)(gx + k0 + 4 * q);
            pwh[0] = *(const uint4*)(gwh + k0);  pwh[1] = *(const uint4*)(gwh + k0 + 8);
            pwl[0] = *(const uint4*)(gwl + k0);  pwl[1] = *(const uint4*)(gwl + k0 + 8);
        }
#pragma unroll
        for (int ks = 0; ks < 4; ks++) {
            const uint32_t koff = ks * 32;
            uint32_t ah0, ah1, ah2, ah3, al0, al1, al2, al3;
            LDSM4(ah0, ah1, ah2, ah3, aHb + koff);
            LDSM4(al0, al1, al2, al3, aLb + koff);
            uint32_t h00, h01, h10, h11, h20, h21, h30, h31;
            LDSM4(h00, h01, h10, h11, bH0 + koff);
            LDSM4(h20, h21, h30, h31, bH1 + koff);
            uint32_t l00, l01, l10, l11, l20, l21, l30, l31;
            LDSM4(l00, l01, l10, l11, bL0 + koff);
            LDSM4(l20, l21, l30, l31, bL1 + koff);
            mma16816(acc[0], ah0, ah1, ah2, ah3, h00, h01);
            mma16816(acc[0], ah0, ah1, ah2, ah3, l00, l01);
            mma16816(acc[0], al0, al1, al2, al3, h00, h01);
            mma16816(acc[1], ah0, ah1, ah2, ah3, h10, h11);
            mma16816(acc[1], ah0, ah1, ah2, ah3, l10, l11);
            mma16816(acc[1], al0, al1, al2, al3, h10, h11);
            mma16816(acc[2], ah0, ah1, ah2, ah3, h20, h21);
            mma16816(acc[2], ah0, ah1, ah2, ah3, l20, l21);
            mma16816(acc[2], al0, al1, al2, al3, h20, h21);
            mma16816(acc[3], ah0, ah1, ah2, ah3, h30, h31);
            mma16816(acc[3], ah0, ah1, ah2, ah3, l30, l31);
            mma16816(acc[3], al0, al1, al2, al3, h30, h31);
        }
        __syncthreads();
    }

    float* lt    = (float*)smraw;          // [64][65]
    float* sbias = lt + 64 * 65;
    int*   sC    = (int*)(sbias + 64);

    {
        const int t0 = 16 * r + gid;
#pragma unroll
        for (int j = 0; j < 4; j++) {
            const int e = 32 * hh + 8 * j + 2 * tid4;
            lt[t0 * 65 + e]           = acc[j][0];
            lt[t0 * 65 + e + 1]       = acc[j][1];
            lt[(t0 + 8) * 65 + e]     = acc[j][2];
            lt[(t0 + 8) * 65 + e + 1] = acc[j][3];
        }
    }
    if (tid < NEXP) { sbias[tid] = bias[tid]; sC[tid] = 0; }
    __syncthreads();

    if (tid < TILE_M) {
        const int j = tid;
        float* rowp = lt + j * 65;

        float ssum = 0.0f;
#pragma unroll 8
        for (int e = 0; e < NEXP; e++) ssum += sigm(rowp[e]);

        unsigned long long used = 0ull;
        int   isel[KSEL];
        float bestv[KSEL + 1];
        float wsel[KSEL];
        float wsum = 0.0f;
        for (int k = 0; k < KSEL + 1; k++) {
            float best = -3.402823466e38f;
            int   bi   = 0;
            for (int e = 0; e < NEXP; e++) {
                if (!((used >> e) & 1ull)) {
                    const float bl = rowp[e] + sbias[e];
                    if (bl > best) { best = bl; bi = e; }
                }
            }
            used |= 1ull << bi;
            bestv[k] = best;
            if (k < KSEL) {
                isel[k] = bi;
                const float sc = sigm(rowp[bi]);
                wsel[k] = sc;
                wsum += sc;
            }
        }
        float minGap = 3.402823466e38f;
#pragma unroll
        for (int k = 0; k < KSEL; k++) {
            const float g = bestv[k] - bestv[k + 1];
            minGap = (g < minGap) ? g : minGap;
        }
        g_flag[m0 + j] = (minGap < TAU) ? 1 : 0;

        const float inv = 1.0f / (wsum + 1e-10f);
        float* oi = out + (size_t)(m0 + j) * KSEL;
        float* ow = out + OUT_W + (size_t)(m0 + j) * KSEL;
#pragma unroll
        for (int k = 0; k < KSEL; k++) {
            oi[k] = (float)isel[k];
            ow[k] = wsel[k] * inv;
            atomicAdd(&sC[isel[k]], 1);
        }
        const float pin = 1.0f / (ssum + 1e-10f);
        for (int e = 0; e < NEXP; e++) rowp[e] = sigm(rowp[e]) * pin;
    }
    __syncthreads();

    if (tid < NEXP) {
        float ps = 0.0f;
        for (int j = 0; j < TILE_M; j++) ps += lt[j * 65 + tid];
        g_Pp[blockIdx.x * NEXP + tid] = ps;
        g_Cp[blockIdx.x * NEXP + tid] = sC[tid];
    }
}

// ========== aux: flag compaction (threads 0-255) + stats reduce (256-511) ==========
__global__ void gate_aux(float* __restrict__ out) {
    __shared__ int   cnt[256];
    __shared__ int   off[256];
    __shared__ float sP[NB][NEXP];
    __shared__ int   sCt[NB][NEXP];
    __shared__ float red[NEXP];
    const int tid = threadIdx.x;

    if (tid < 256) {
        const int per = NTOK / 256;    // 64
        int c = 0;
        for (int i = 0; i < per; i++) c += g_flag[tid * per + i];
        cnt[tid] = c;
    } else {
        const int t2 = tid - 256;
        const int e = t2 & 63, b = t2 >> 6;
        int   cb = 0;
        float pb = 0.0f;
        const int base = b * (SEQ / TILE_M);
        for (int blk = 0; blk < SEQ / TILE_M; blk++) {
            const int g = (base + blk) * NEXP + e;
            cb += g_Cp[g];
            pb += g_Pp[g];
        }
        sCt[b][e] = cb;
        sP[b][e]  = pb;
    }
    __syncthreads();

    if (tid == 0) {
        int r = 0;
        for (int i = 0; i < 256; i++) { off[i] = r; r += cnt[i]; }
        g_nflag = r;
    }
    if (tid >= 256 && tid < 256 + NEXP) {
        const int e = tid - 256;
        long long load = 0;
        float part = 0.0f;
        for (int bb = 0; bb < NB; bb++) {
            const int c = sCt[bb][e];
            load += c;
            const float fi = (float)c / (float)(KSEL * SEQ);
            const float Pi = sP[bb][e] / (float)SEQ;
            part += fi * Pi;
        }
        out[OUT_LOAD + e] = (float)load;
        red[e] = part;
    }
    __syncthreads();

    if (tid < 256) {
        const int per = NTOK / 256;
        int o = off[tid];
        for (int i = 0; i < per; i++) {
            const int t = tid * per + i;
            if (g_flag[t]) g_list[o++] = t;
        }
    }
    if (tid == 511) {
        float s = 0.0f;
        for (int i = 0; i < NEXP; i++) s += red[i];
        out[OUT_LOSS] = 0.01f * s / (float)NB;   // SEQ_ALPHA * mean over batch
    }
}

// ===== pass 2: ensemble re-vote; cp.async depth-4 w pipeline, chains unchanged =====
__global__ __launch_bounds__(64, 4)
void gate_vote(const float* __restrict__ x,
               const float* __restrict__ bias,
               float* __restrict__ out) {
    __shared__ __align__(16) float sx[HDIM];          // 8 KB
    __shared__ __align__(16) float swb[4][32 * 64];   // 4-stage ring, 32 KB
    __shared__ float sL[NEXP];
    const int tid = threadIdx.x;
    const int nf = g_nflag;

    for (int idx = blockIdx.x; idx < nf; idx += VGRID) {
        const int tok = g_list[idx];
        __syncthreads();   // protect sx/sL/swb reuse across iterations
        {
            const float4* gx4 = (const float4*)(x + (size_t)tok * HDIM);
            float4* sx4 = (float4*)sx;
#pragma unroll
            for (int q = 0; q < 8; q++) sx4[q * 64 + tid] = gx4[q * 64 + tid];
        }
        // prologue: stages 0..2 (w chunk = contiguous 8KB of g_wT)
#pragma unroll
        for (int s = 0; s < 3; s++) {
            const float* gsrc = g_wT + s * (32 * NEXP) + tid * 4;
            const uint32_t sdst = sptr(&swb[s][0]) + tid * 16;
#pragma unroll
            for (int i = 0; i < 8; i++)
                CPASYNC16(sdst + i * 1024, gsrc + i * 256);
            CP_COMMIT();
        }

        float aS = 0.0f, aH = 0.0f, aQ = 0.0f;
        float g16a = 0, g16b = 0, g16c = 0, g16d = 0;
        float g32_0 = 0, g32_1 = 0, g32_2 = 0, g32_3 = 0,
              g32_4 = 0, g32_5 = 0, g32_6 = 0, g32_7 = 0;
        float p2_0 = 0, p4_0 = 0, p4_1 = 0, p4_2 = 0;

        for (int c = 0; c < HDIM / 32; c++) {
            CP_WAIT2();          // stage c complete
            __syncthreads();     // visible across both warps
            const float* wrow = &swb[c & 3][0];
            const float* xrow = &sx[c * 32];
#pragma unroll
            for (int kk = 0; kk < 32; kk++) {
                const float xa = xrow[kk];
                const float wa = wrow[kk * 64 + tid];
                aS = fmaf(xa, wa, aS);
                aH = fmaf(xa, wa, aH);
                aQ = fmaf(xa, wa, aQ);
                const int q = kk >> 2;
                if ((q & 3) == 0)      g16a = fmaf(xa, wa, g16a);
                else if ((q & 3) == 1) g16b = fmaf(xa, wa, g16b);
                else if ((q & 3) == 2) g16c = fmaf(xa, wa, g16c);
                else                   g16d = fmaf(xa, wa, g16d);
                if      (q == 0) g32_0 = fmaf(xa, wa, g32_0);
                else if (q == 1) g32_1 = fmaf(xa, wa, g32_1);
                else if (q == 2) g32_2 = fmaf(xa, wa, g32_2);
                else if (q == 3) g32_3 = fmaf(xa, wa, g32_3);
                else if (q == 4) g32_4 = fmaf(xa, wa, g32_4);
                else if (q == 5) g32_5 = fmaf(xa, wa, g32_5);
                else if (q == 6) g32_6 = fmaf(xa, wa, g32_6);
                else             g32_7 = fmaf(xa, wa, g32_7);
            }
            if (c == 15) { p4_0 = aQ; aQ = 0.0f; }
            if (c == 31) { p4_1 = aQ; aQ = 0.0f; p2_0 = aH; aH = 0.0f; }
            if (c == 47) { p4_2 = aQ; aQ = 0.0f; }
            // issue stage c+3 (buffer (c+3)&3 was fully consumed at chunk c-1)
            if (c + 3 < HDIM / 32) {
                const float* gsrc = g_wT + (c + 3) * (32 * NEXP) + tid * 4;
                const uint32_t sdst = sptr(&swb[(c + 3) & 3][0]) + tid * 16;
#pragma unroll
                for (int i = 0; i < 8; i++)
                    CPASYNC16(sdst + i * 1024, gsrc + i * 256);
            }
            CP_COMMIT();         // commit even when empty: keeps group accounting fixed
        }
        CP_WAIT0();              // drain before next token reuses the ring

        {
            const float L1 = aS;
            const float L2 = (g16a + g16c) + (g16b + g16d);
            const float L3 = p2_0 + aH;
            const float L4 = ((p4_0 + p4_1) + p4_2) + aQ;
            const float L5 = ((g32_0 + g32_1) + (g32_2 + g32_3))
                           + ((g32_4 + g32_5) + (g32_6 + g32_7));
            float v[5] = {L1, L2, L3, L4, L5};
#pragma unroll
            for (int a = 0; a < 4; a++)
#pragma unroll
                for (int b = 0; b < 4 - a; b++)
                    if (v[b] > v[b + 1]) { const float t = v[b]; v[b] = v[b + 1]; v[b + 1] = t; }
            sL[tid] = v[2];
        }
        __syncthreads();

        if (tid == 0) {
            unsigned long long used = 0ull;
            int   isel[KSEL];
            float wsel[KSEL];
            float wsum = 0.0f;
            for (int k = 0; k < KSEL; k++) {
                float best = -3.402823466e38f;
                int   bi   = 0;
                for (int e = 0; e < NEXP; e++) {
                    if (!((used >> e) & 1ull)) {
                        const float bl = sL[e] + __ldg(bias + e);
                        if (bl > best) { best = bl; bi = e; }
                    }
                }
                used |= 1ull << bi;
                isel[k] = bi;
                const float sc = sigm(sL[bi]);
                wsel[k] = sc;
                wsum += sc;
            }
            const float inv = 1.0f / (wsum + 1e-10f);
            for (int k = 0; k < KSEL; k++) {
                out[(size_t)tok * KSEL + k]         = (float)isel[k];
                out[OUT_W + (size_t)tok * KSEL + k] = wsel[k] * inv;
            }
        }
    }
}

extern "C" void kernel_launch(void* const* d_in, const int* in_sizes, int n_in,
                              void* d_out, int out_size) {
    const float* x    = (const float*)d_in[0];
    const float* w    = (const float*)d_in[1];
    const float* bias = (const float*)d_in[2];
    float* out = (float*)d_out;
    (void)in_sizes; (void)n_in; (void)out_size;

    wcvt<<<128, 256>>>(w);
    gate_main<<<NBLK, 256>>>(x, bias, out);
    gate_aux<<<1, 512>>>(out);
    gate_vote<<<VGRID, 64>>>(x, bias, out);
}